// round 3
// baseline (speedup 1.0000x reference)
#include <cuda_runtime.h>
#include <float.h>
#include <math.h>

#define BATCH 2
#define NSEQ  2048
#define DIM   1024
#define H     16
#define DH    64
#define NM    16
#define JTOT  2064          // NM + NSEQ
#define MROWS (BATCH*NSEQ)  // 4096

// ---------------- global scratch (static __device__, no allocations) ----------------
__device__ float g_Q[BATCH][H][NSEQ][DH];      // ~16.8 MB
__device__ float g_K[BATCH][H][JTOT][DH];      // ~16.9 MB (mem_k prepended)
__device__ float g_V[BATCH][H][JTOT][DH];      // ~16.9 MB
__device__ float g_dots[BATCH][H][NSEQ][JTOT]; // ~541 MB raw per-head dots
__device__ float g_ctx[BATCH][NSEQ][H*DH];     // ~16.8 MB attention output

// ---------------- fill mem_k / mem_v into K/V prefix ----------------
__global__ void memfill_kernel(const float* __restrict__ mk, const float* __restrict__ mv) {
    int idx = blockIdx.x * 256 + threadIdx.x;
    if (idx >= BATCH * H * NM * DH) return;
    int d = idx & 63;
    int j = (idx >> 6) & 15;
    int h = (idx >> 10) & 15;
    int b = idx >> 14;
    g_K[b][h][j][d] = mk[(h * NM + j) * DH + d];
    g_V[b][h][j][d] = mv[(h * NM + j) * DH + d];
}

// ---------------- QKV projection: x(4096x1024) @ W(1024x1024), 3 weights ----------------
__global__ __launch_bounds__(256) void gemm_qkv_kernel(
    const float* __restrict__ x, const float* __restrict__ Wq,
    const float* __restrict__ Wk, const float* __restrict__ Wv) {
    const int z = blockIdx.z;
    const float* W = (z == 0) ? Wq : (z == 1) ? Wk : Wv;
    __shared__ float As[32][68];  // As[k][m] (transposed)
    __shared__ float Bs[32][68];  // Bs[k][n]
    const int m0 = blockIdx.y << 6;
    const int n0 = blockIdx.x << 6;
    const int tid = threadIdx.x;
    const int ty = tid >> 4, tx = tid & 15;
    const int ar = tid >> 3, ac = (tid & 7) << 2;
    const int br = tid >> 4, bc = (tid & 15) << 2;
    float acc[4][4];
#pragma unroll
    for (int i = 0; i < 4; i++)
#pragma unroll
        for (int j = 0; j < 4; j++) acc[i][j] = 0.f;

    for (int k0 = 0; k0 < DIM; k0 += 32) {
        float4 a0 = *(const float4*)&x[(m0 + ar) * DIM + k0 + ac];
        float4 a1 = *(const float4*)&x[(m0 + ar + 32) * DIM + k0 + ac];
        float4 b0 = *(const float4*)&W[(k0 + br) * DIM + n0 + bc];
        float4 b1 = *(const float4*)&W[(k0 + br + 16) * DIM + n0 + bc];
        __syncthreads();
        As[ac + 0][ar] = a0.x; As[ac + 1][ar] = a0.y; As[ac + 2][ar] = a0.z; As[ac + 3][ar] = a0.w;
        As[ac + 0][ar + 32] = a1.x; As[ac + 1][ar + 32] = a1.y; As[ac + 2][ar + 32] = a1.z; As[ac + 3][ar + 32] = a1.w;
        *(float4*)&Bs[br][bc] = b0;
        *(float4*)&Bs[br + 16][bc] = b1;
        __syncthreads();
#pragma unroll
        for (int kk = 0; kk < 32; kk++) {
            float4 av = *(const float4*)&As[kk][ty << 2];
            float4 bv = *(const float4*)&Bs[kk][tx << 2];
            float a[4] = {av.x, av.y, av.z, av.w};
            float bb[4] = {bv.x, bv.y, bv.z, bv.w};
#pragma unroll
            for (int i = 0; i < 4; i++)
#pragma unroll
                for (int j = 0; j < 4; j++) acc[i][j] += a[i] * bb[j];
        }
    }
    // epilogue: scatter to head-major layout
#pragma unroll
    for (int i = 0; i < 4; i++) {
        int m = m0 + (ty << 2) + i;
        int b = m >> 11;
        int irow = m & 2047;
        int c = n0 + (tx << 2);
        int h = c >> 6;
        int d = c & 63;
        float4 v = make_float4(acc[i][0], acc[i][1], acc[i][2], acc[i][3]);
        if (z == 0)      *(float4*)&g_Q[b][h][irow][d] = v;
        else if (z == 1) *(float4*)&g_K[b][h][NM + irow][d] = v;
        else             *(float4*)&g_V[b][h][NM + irow][d] = v;
    }
}

// ---------------- raw dots: per (b,h), dots[i][j] = scale * Q[i]·K[j], causal tile-skip ----------------
__global__ __launch_bounds__(256) void dots_kernel() {
    const int bh = blockIdx.z;
    const int b = bh >> 4, h = bh & 15;
    const int i0 = blockIdx.y << 6;
    const int j0 = blockIdx.x << 6;
    if (j0 > i0 + 63 + NM) return;  // entire tile causally masked
    __shared__ float Qs[64][68];  // Qs[d][i]
    __shared__ float Ks[64][68];  // Ks[d][j]
    const int tid = threadIdx.x;
    const int ty = tid >> 4, tx = tid & 15;
    const int lr = tid >> 4;
    const int lc = (tid & 15) << 2;
#pragma unroll
    for (int rr = 0; rr < 64; rr += 16) {
        float4 q = *(const float4*)&g_Q[b][h][i0 + lr + rr][lc];
        Qs[lc + 0][lr + rr] = q.x; Qs[lc + 1][lr + rr] = q.y;
        Qs[lc + 2][lr + rr] = q.z; Qs[lc + 3][lr + rr] = q.w;
        int j = j0 + lr + rr;
        float4 kv = make_float4(0.f, 0.f, 0.f, 0.f);
        if (j < JTOT) kv = *(const float4*)&g_K[b][h][j][lc];
        Ks[lc + 0][lr + rr] = kv.x; Ks[lc + 1][lr + rr] = kv.y;
        Ks[lc + 2][lr + rr] = kv.z; Ks[lc + 3][lr + rr] = kv.w;
    }
    __syncthreads();
    float acc[4][4];
#pragma unroll
    for (int i = 0; i < 4; i++)
#pragma unroll
        for (int j = 0; j < 4; j++) acc[i][j] = 0.f;
#pragma unroll
    for (int kk = 0; kk < 64; kk++) {
        float4 av = *(const float4*)&Qs[kk][ty << 2];
        float4 bv = *(const float4*)&Ks[kk][tx << 2];
        float a[4] = {av.x, av.y, av.z, av.w};
        float bb[4] = {bv.x, bv.y, bv.z, bv.w};
#pragma unroll
        for (int i = 0; i < 4; i++)
#pragma unroll
            for (int j = 0; j < 4; j++) acc[i][j] += a[i] * bb[j];
    }
    const float scale = 0.125f;  // dh^-0.5
#pragma unroll
    for (int i = 0; i < 4; i++) {
        int irow = i0 + (ty << 2) + i;
        int jcol = j0 + (tx << 2);
        if (jcol < JTOT) {
            float4 v = make_float4(acc[i][0] * scale, acc[i][1] * scale,
                                   acc[i][2] * scale, acc[i][3] * scale);
            *(float4*)&g_dots[b][h][irow][jcol] = v;
        }
    }
}

// ---------------- fused per-row attention: premix, mask, top8, softmax, postmix, sparse AV ----------------
#define ATTN_SMEM_FLOATS (H*JTOT + 256 + 256 + 2048 + 16 + 256)
#define ATTN_SMEM_INTS   (JTOT + JTOT + 256)
#define ATTN_SMEM_BYTES  ((ATTN_SMEM_FLOATS + ATTN_SMEM_INTS) * 4)

__global__ __launch_bounds__(256) void attn_kernel(
    const float* __restrict__ pre, const float* __restrict__ post) {
    const int i = blockIdx.x;
    const int b = blockIdx.y;
    const int tid = threadIdx.x;
    extern __shared__ float sm[];
    float* s_d    = sm;                    // [16][2064] dots -> attn -> attn2
    float* s_pre  = s_d + H * JTOT;        // [16][16]
    float* s_post = s_pre + 256;           // [16][16]
    float* s_top  = s_post + 256;          // [16 rows][16 lists][8]
    float* s_sum  = s_top + 2048;          // [16]
    float* s_red  = s_sum + 16;            // [256]
    int* s_flag = (int*)(s_red + 256);     // [2064]
    int* s_list = s_flag + JTOT;           // [2064]
    int* s_scan = s_list + JTOT;           // [256]

    s_pre[tid]  = pre[tid];
    s_post[tid] = post[tid];
    const int nv = i + NM + 1;  // valid j: [0, nv)

    // load raw dots (valid range only)
    for (int h = 0; h < H; h++) {
        const float* src = &g_dots[b][h][i][0];
        float* dst = s_d + h * JTOT;
        for (int j = tid; j < nv; j += 256) dst[j] = src[j];
    }
    for (int j = tid; j < JTOT; j += 256) s_flag[j] = 0;
    __syncthreads();

    // premix across heads (in place per column) + causal mask
    for (int j = tid; j < JTOT; j += 256) {
        if (j < nv) {
            float r[16];
#pragma unroll
            for (int h2 = 0; h2 < 16; h2++) r[h2] = s_d[h2 * JTOT + j];
#pragma unroll
            for (int k = 0; k < 16; k++) {
                float a = 0.f;
#pragma unroll
                for (int h2 = 0; h2 < 16; h2++) a += r[h2] * s_pre[h2 * 16 + k];
                s_d[k * JTOT + j] = a;
            }
        } else {
#pragma unroll
            for (int k = 0; k < 16; k++) s_d[k * JTOT + j] = -FLT_MAX;
        }
    }
    __syncthreads();

    // ---- top-8 per row (16 threads per row) ----
    const int row = tid >> 4;
    const int t = tid & 15;
    const float* rd = s_d + row * JTOT;
    float t8[8];
#pragma unroll
    for (int q = 0; q < 8; q++) t8[q] = -FLT_MAX;
    for (int j = t; j < nv; j += 16) {
        float v = rd[j];
        if (v > t8[7]) {
            t8[7] = v;
#pragma unroll
            for (int q = 7; q >= 1; q--) {
                if (t8[q] > t8[q - 1]) { float tmp = t8[q]; t8[q] = t8[q - 1]; t8[q - 1] = tmp; }
            }
        }
    }
    {
        float* myl = s_top + (row * 16 + t) * 8;
#pragma unroll
        for (int q = 0; q < 8; q++) myl[q] = t8[q];
    }
    __syncthreads();
    // merge-tree: 16 sorted lists -> 1 (smem 2-pointer merges, deterministic)
#pragma unroll
    for (int L = 8; L >= 1; L >>= 1) {
        if (t < L) {
            float* A  = s_top + (row * 16 + t) * 8;
            float* B2 = s_top + (row * 16 + t + L) * 8;
            float out[8];
            int ia = 0, ib = 0;
#pragma unroll
            for (int r2 = 0; r2 < 8; r2++) {
                float va = A[ia];
                float vb = B2[ib];
                bool ta = (va >= vb);
                out[r2] = ta ? va : vb;
                ia += ta ? 1 : 0;
                ib += ta ? 0 : 1;
            }
#pragma unroll
            for (int r2 = 0; r2 < 8; r2++) A[r2] = out[r2];
        }
        __syncthreads();
    }
    const float thr = s_top[row * 128 + 7];
    const float mx  = s_top[row * 128 + 0];

    // ---- sum of exp over kept + set union flags ----
    float psum = 0.f;
    for (int j = t; j < nv; j += 16) {
        float v = rd[j];
        if (v >= thr) { psum += __expf(v - mx); s_flag[j] = 1; }
    }
    s_red[tid] = psum;
    __syncthreads();
    if (t == 0) {
        float s = 0.f;
#pragma unroll
        for (int q = 0; q < 16; q++) s += s_red[row * 16 + q];
        s_sum[row] = s;
    }
    __syncthreads();

    // ---- normalize (in place): attn values, zeros elsewhere ----
    {
        const float inv = 1.f / s_sum[row];
        float* wrow = s_d + row * JTOT;
        for (int j = t; j < nv; j += 16) {
            float v = wrow[j];
            wrow[j] = (v >= thr) ? __expf(v - mx) * inv : 0.f;
        }
    }
    __syncthreads();

    // ---- deterministic survivor compaction (chunk + prefix scan) ----
    const int CH = 9;  // 256*9 >= 2064
    int base = tid * CH;
    int end = base + CH; if (end > nv) end = nv;
    int c = 0;
    for (int j = base; j < end; j++) c += s_flag[j];
    s_scan[tid] = c;
    __syncthreads();
    for (int off = 1; off < 256; off <<= 1) {
        int v = s_scan[tid];
        int add = (tid >= off) ? s_scan[tid - off] : 0;
        __syncthreads();
        s_scan[tid] = v + add;
        __syncthreads();
    }
    {
        int pos = s_scan[tid] - c;
        for (int j = base; j < end; j++)
            if (s_flag[j]) s_list[pos++] = j;
    }
    __syncthreads();
    const int cnt = s_scan[255];

    // ---- post-mix at survivor columns only (in place) ----
    for (int sI = tid; sI < cnt; sI += 256) {
        int j = s_list[sI];
        float a[16];
#pragma unroll
        for (int h2 = 0; h2 < 16; h2++) a[h2] = s_d[h2 * JTOT + j];
#pragma unroll
        for (int k = 0; k < 16; k++) {
            float acc2 = 0.f;
#pragma unroll
            for (int h2 = 0; h2 < 16; h2++) acc2 += a[h2] * s_post[h2 * 16 + k];
            s_d[k * JTOT + j] = acc2;
        }
    }
    __syncthreads();

    // ---- sparse attn2 @ V: thread owns (k, 4 dims) ----
    const int kk2 = tid >> 4;
    const int d4 = (tid & 15) << 2;
    float ax = 0.f, ay = 0.f, az = 0.f, aw = 0.f;
    const float* Vb = &g_V[b][kk2][0][0];
    const float* wr = s_d + kk2 * JTOT;
    int s2 = 0;
    for (; s2 + 1 < cnt; s2 += 2) {
        int ja = s_list[s2], jb = s_list[s2 + 1];
        float wa = wr[ja], wb = wr[jb];
        float4 va = *(const float4*)(Vb + ja * 64 + d4);
        float4 vb = *(const float4*)(Vb + jb * 64 + d4);
        ax += wa * va.x + wb * vb.x;
        ay += wa * va.y + wb * vb.y;
        az += wa * va.z + wb * vb.z;
        aw += wa * va.w + wb * vb.w;
    }
    if (s2 < cnt) {
        int ja = s_list[s2];
        float wa = wr[ja];
        float4 va = *(const float4*)(Vb + ja * 64 + d4);
        ax += wa * va.x; ay += wa * va.y; az += wa * va.z; aw += wa * va.w;
    }
    float4 o = make_float4(ax, ay, az, aw);
    *(float4*)&g_ctx[b][i][kk2 * 64 + d4] = o;
}

// ---------------- output projection: ctx(4096x1024) @ Wo + bo ----------------
__global__ __launch_bounds__(256) void out_gemm_kernel(
    const float* __restrict__ Wo, const float* __restrict__ bo, float* __restrict__ out) {
    const float* A = &g_ctx[0][0][0];
    __shared__ float As[32][68];
    __shared__ float Bs[32][68];
    const int m0 = blockIdx.y << 6;
    const int n0 = blockIdx.x << 6;
    const int tid = threadIdx.x;
    const int ty = tid >> 4, tx = tid & 15;
    const int ar = tid >> 3, ac = (tid & 7) << 2;
    const int br = tid >> 4, bc = (tid & 15) << 2;
    float acc[4][4];
#pragma unroll
    for (int i = 0; i < 4; i++)
#pragma unroll
        for (int j = 0; j < 4; j++) acc[i][j] = 0.f;

    for (int k0 = 0; k0 < DIM; k0 += 32) {
        float4 a0 = *(const float4*)&A[(m0 + ar) * DIM + k0 + ac];
        float4 a1 = *(const float4*)&A[(m0 + ar + 32) * DIM + k0 + ac];
        float4 b0 = *(const float4*)&Wo[(k0 + br) * DIM + n0 + bc];
        float4 b1 = *(const float4*)&Wo[(k0 + br + 16) * DIM + n0 + bc];
        __syncthreads();
        As[ac + 0][ar] = a0.x; As[ac + 1][ar] = a0.y; As[ac + 2][ar] = a0.z; As[ac + 3][ar] = a0.w;
        As[ac + 0][ar + 32] = a1.x; As[ac + 1][ar + 32] = a1.y; As[ac + 2][ar + 32] = a1.z; As[ac + 3][ar + 32] = a1.w;
        *(float4*)&Bs[br][bc] = b0;
        *(float4*)&Bs[br + 16][bc] = b1;
        __syncthreads();
#pragma unroll
        for (int kk = 0; kk < 32; kk++) {
            float4 av = *(const float4*)&As[kk][ty << 2];
            float4 bv = *(const float4*)&Bs[kk][tx << 2];
            float a[4] = {av.x, av.y, av.z, av.w};
            float bb[4] = {bv.x, bv.y, bv.z, bv.w};
#pragma unroll
            for (int i = 0; i < 4; i++)
#pragma unroll
                for (int j = 0; j < 4; j++) acc[i][j] += a[i] * bb[j];
        }
    }
#pragma unroll
    for (int i = 0; i < 4; i++) {
        int m = m0 + (ty << 2) + i;
        int c = n0 + (tx << 2);
        float4 bias = *(const float4*)&bo[c];
        float4 v = make_float4(acc[i][0] + bias.x, acc[i][1] + bias.y,
                               acc[i][2] + bias.z, acc[i][3] + bias.w);
        *(float4*)&out[m * DIM + c] = v;
    }
}

// ---------------- launch ----------------
extern "C" void kernel_launch(void* const* d_in, const int* in_sizes, int n_in,
                              void* d_out, int out_size) {
    const float* x    = (const float*)d_in[0];
    const float* Wq   = (const float*)d_in[1];
    const float* Wk   = (const float*)d_in[2];
    const float* Wv   = (const float*)d_in[3];
    const float* pre  = (const float*)d_in[4];
    const float* post = (const float*)d_in[5];
    const float* mk   = (const float*)d_in[6];
    const float* mv   = (const float*)d_in[7];
    const float* Wo   = (const float*)d_in[8];
    const float* bo   = (const float*)d_in[9];
    float* out = (float*)d_out;

    cudaFuncSetAttribute(attn_kernel, cudaFuncAttributeMaxDynamicSharedMemorySize, ATTN_SMEM_BYTES);

    memfill_kernel<<<(BATCH * H * NM * DH + 255) / 256, 256>>>(mk, mv);
    gemm_qkv_kernel<<<dim3(DIM / 64, MROWS / 64, 3), 256>>>(x, Wq, Wk, Wv);
    dots_kernel<<<dim3((JTOT + 63) / 64, NSEQ / 64, BATCH * H), 256>>>();
    attn_kernel<<<dim3(NSEQ, BATCH), 256, ATTN_SMEM_BYTES>>>(pre, post);
    out_gemm_kernel<<<dim3(DIM / 64, MROWS / 64), 256>>>(Wo, bo, out);
}

// round 4
// speedup vs baseline: 1.1964x; 1.1964x over previous
#include <cuda_runtime.h>
#include <float.h>
#include <math.h>

#define BATCH 2
#define NSEQ  2048
#define DIM   1024
#define H     16
#define DH    64
#define NM    16
#define JTOT  2064          // NM + NSEQ
#define MROWS (BATCH*NSEQ)  // 4096

// ---------------- global scratch ----------------
__device__ float g_Q[BATCH][H][NSEQ][DH];
__device__ float g_K[BATCH][H][JTOT][DH];
__device__ float g_V[BATCH][H][JTOT][DH];
__device__ float g_dots[BATCH][H][NSEQ][JTOT];
__device__ float g_ctx[BATCH][NSEQ][H*DH];

// ---------------- fill mem_k / mem_v into K/V prefix ----------------
__global__ void memfill_kernel(const float* __restrict__ mk, const float* __restrict__ mv) {
    int idx = blockIdx.x * 256 + threadIdx.x;
    if (idx >= BATCH * H * NM * DH) return;
    int d = idx & 63;
    int j = (idx >> 6) & 15;
    int h = (idx >> 10) & 15;
    int b = idx >> 14;
    g_K[b][h][j][d] = mk[(h * NM + j) * DH + d];
    g_V[b][h][j][d] = mv[(h * NM + j) * DH + d];
}

// ============ 128x128x16 fp32 GEMM: QKV projection ============
__global__ __launch_bounds__(256, 2) void gemm_qkv_kernel(
    const float* __restrict__ x, const float* __restrict__ Wq,
    const float* __restrict__ Wk, const float* __restrict__ Wv) {
    const int z = blockIdx.z;
    const float* W = (z == 0) ? Wq : (z == 1) ? Wk : Wv;
    __shared__ float As[16][132];
    __shared__ float Bs[16][132];
    const int m0 = blockIdx.y << 7;
    const int n0 = blockIdx.x << 7;
    const int tid = threadIdx.x;
    const int ty = tid >> 4, tx = tid & 15;
    const int arow = tid >> 2, acol = (tid & 3) << 2;
    const int brow = tid >> 5, bcol = (tid & 31) << 2;
    float acc[8][8];
#pragma unroll
    for (int i = 0; i < 8; i++)
#pragma unroll
        for (int j = 0; j < 8; j++) acc[i][j] = 0.f;

    for (int k0 = 0; k0 < DIM; k0 += 16) {
        float4 a0 = *(const float4*)&x[(m0 + arow) * DIM + k0 + acol];
        float4 a1 = *(const float4*)&x[(m0 + arow + 64) * DIM + k0 + acol];
        float4 b0 = *(const float4*)&W[(k0 + brow) * DIM + n0 + bcol];
        float4 b1 = *(const float4*)&W[(k0 + brow + 8) * DIM + n0 + bcol];
        __syncthreads();
        As[acol + 0][arow] = a0.x; As[acol + 1][arow] = a0.y;
        As[acol + 2][arow] = a0.z; As[acol + 3][arow] = a0.w;
        As[acol + 0][arow + 64] = a1.x; As[acol + 1][arow + 64] = a1.y;
        As[acol + 2][arow + 64] = a1.z; As[acol + 3][arow + 64] = a1.w;
        *(float4*)&Bs[brow][bcol] = b0;
        *(float4*)&Bs[brow + 8][bcol] = b1;
        __syncthreads();
#pragma unroll
        for (int kk = 0; kk < 16; kk++) {
            float4 a04 = *(const float4*)&As[kk][ty << 3];
            float4 a14 = *(const float4*)&As[kk][(ty << 3) + 4];
            float4 b04 = *(const float4*)&Bs[kk][tx << 3];
            float4 b14 = *(const float4*)&Bs[kk][(tx << 3) + 4];
            float av[8] = {a04.x, a04.y, a04.z, a04.w, a14.x, a14.y, a14.z, a14.w};
            float bv[8] = {b04.x, b04.y, b04.z, b04.w, b14.x, b14.y, b14.z, b14.w};
#pragma unroll
            for (int i = 0; i < 8; i++)
#pragma unroll
                for (int j = 0; j < 8; j++) acc[i][j] += av[i] * bv[j];
        }
    }
#pragma unroll
    for (int i = 0; i < 8; i++) {
        int m = m0 + (ty << 3) + i;
        int b = m >> 11;
        int irow = m & 2047;
#pragma unroll
        for (int j2 = 0; j2 < 8; j2 += 4) {
            int c = n0 + (tx << 3) + j2;
            int h = c >> 6;
            int d = c & 63;
            float4 v = make_float4(acc[i][j2], acc[i][j2 + 1], acc[i][j2 + 2], acc[i][j2 + 3]);
            if (z == 0)      *(float4*)&g_Q[b][h][irow][d] = v;
            else if (z == 1) *(float4*)&g_K[b][h][NM + irow][d] = v;
            else             *(float4*)&g_V[b][h][NM + irow][d] = v;
        }
    }
}

// ============ dots: per (b,h) 128x128x64 tiles, causal skip ============
__global__ __launch_bounds__(256, 2) void dots_kernel() {
    const int bh = blockIdx.z;
    const int b = bh >> 4, h = bh & 15;
    const int i0 = blockIdx.y << 7;
    const int j0 = blockIdx.x << 7;
    if (j0 > i0 + 127 + NM) return;  // entire tile causally masked
    __shared__ float Qs[64][132];  // Qs[d][i]
    __shared__ float Ks[64][132];  // Ks[d][j]
    const int tid = threadIdx.x;
    const int ty = tid >> 4, tx = tid & 15;
    const int lr = tid >> 4;
    const int lc = (tid & 15) << 2;
#pragma unroll
    for (int rr = 0; rr < 128; rr += 16) {
        int r = lr + rr;
        float4 q = *(const float4*)&g_Q[b][h][i0 + r][lc];
        Qs[lc + 0][r] = q.x; Qs[lc + 1][r] = q.y;
        Qs[lc + 2][r] = q.z; Qs[lc + 3][r] = q.w;
        int j = j0 + r;
        float4 kv = make_float4(0.f, 0.f, 0.f, 0.f);
        if (j < JTOT) kv = *(const float4*)&g_K[b][h][j][lc];
        Ks[lc + 0][r] = kv.x; Ks[lc + 1][r] = kv.y;
        Ks[lc + 2][r] = kv.z; Ks[lc + 3][r] = kv.w;
    }
    __syncthreads();
    float acc[8][8];
#pragma unroll
    for (int i = 0; i < 8; i++)
#pragma unroll
        for (int j = 0; j < 8; j++) acc[i][j] = 0.f;
#pragma unroll
    for (int kk = 0; kk < 64; kk++) {
        float4 a04 = *(const float4*)&Qs[kk][ty << 3];
        float4 a14 = *(const float4*)&Qs[kk][(ty << 3) + 4];
        float4 b04 = *(const float4*)&Ks[kk][tx << 3];
        float4 b14 = *(const float4*)&Ks[kk][(tx << 3) + 4];
        float av[8] = {a04.x, a04.y, a04.z, a04.w, a14.x, a14.y, a14.z, a14.w};
        float bv[8] = {b04.x, b04.y, b04.z, b04.w, b14.x, b14.y, b14.z, b14.w};
#pragma unroll
        for (int i = 0; i < 8; i++)
#pragma unroll
            for (int j = 0; j < 8; j++) acc[i][j] += av[i] * bv[j];
    }
    const float scale = 0.125f;
#pragma unroll
    for (int i = 0; i < 8; i++) {
        int irow = i0 + (ty << 3) + i;
#pragma unroll
        for (int j2 = 0; j2 < 8; j2 += 4) {
            int jcol = j0 + (tx << 3) + j2;
            if (jcol < JTOT) {
                float4 v = make_float4(acc[i][j2] * scale, acc[i][j2 + 1] * scale,
                                       acc[i][j2 + 2] * scale, acc[i][j2 + 3] * scale);
                *(float4*)&g_dots[b][h][irow][jcol] = v;
            }
        }
    }
}

// ============ fused per-row attention (512 threads, warp-per-row top-k) ============
#define ATTN_SMEM_FLOATS (H*JTOT + 256 + 256 + 4096 + 16)
#define ATTN_SMEM_INTS   (JTOT + JTOT)
#define ATTN_SMEM_BYTES  ((ATTN_SMEM_FLOATS + ATTN_SMEM_INTS) * 4)

__global__ __launch_bounds__(512) void attn_kernel(
    const float* __restrict__ pre, const float* __restrict__ post) {
    const int i = blockIdx.x;
    const int b = blockIdx.y;
    const int tid = threadIdx.x;
    extern __shared__ float sm[];
    float* s_d    = sm;                    // [16][2064]
    float* s_pre  = s_d + H * JTOT;        // [16][16]
    float* s_post = s_pre + 256;           // [16][16]
    float* s_top  = s_post + 256;          // [16 rows][32 lists][8]
    float* s_wsum = s_top + 4096;          // [16] warp scan sums
    int* s_flag = (int*)(s_wsum + 16);     // [2064]
    int* s_list = s_flag + JTOT;           // [2064]

    if (tid < 256) { s_pre[tid] = pre[tid]; s_post[tid] = post[tid]; }
    const int nv = i + NM + 1;

    // load raw dots, float4 main + scalar tail
    {
        const int n4 = nv >> 2;
        for (int h = 0; h < H; h++) {
            const float* src = &g_dots[b][h][i][0];
            float* dst = s_d + h * JTOT;
            for (int j = tid; j < n4; j += 512)
                *(float4*)&dst[j << 2] = *(const float4*)&src[j << 2];
            int jt = (n4 << 2) + tid;
            if (jt < nv) dst[jt] = src[jt];
        }
    }
    for (int j = tid; j < JTOT; j += 512) s_flag[j] = 0;
    __syncthreads();

    // premix across heads + causal fill
    for (int j = tid; j < JTOT; j += 512) {
        if (j < nv) {
            float r[16];
#pragma unroll
            for (int h2 = 0; h2 < 16; h2++) r[h2] = s_d[h2 * JTOT + j];
#pragma unroll
            for (int k = 0; k < 16; k++) {
                float a = 0.f;
#pragma unroll
                for (int h2 = 0; h2 < 16; h2++) a += r[h2] * s_pre[h2 * 16 + k];
                s_d[k * JTOT + j] = a;
            }
        } else {
#pragma unroll
            for (int k = 0; k < 16; k++) s_d[k * JTOT + j] = -FLT_MAX;
        }
    }
    __syncthreads();

    // ---- top-8 per row: each row owned by exactly one warp ----
    const int row = tid >> 5;   // warp id == row
    const int t = tid & 31;     // lane
    const float* rd = s_d + row * JTOT;
    float t8[8];
#pragma unroll
    for (int q = 0; q < 8; q++) t8[q] = -FLT_MAX;
    for (int j = t; j < nv; j += 32) {
        float v = rd[j];
        if (v > t8[7]) {
            t8[7] = v;
#pragma unroll
            for (int q = 7; q >= 1; q--) {
                if (t8[q] > t8[q - 1]) { float tmp = t8[q]; t8[q] = t8[q - 1]; t8[q - 1] = tmp; }
            }
        }
    }
    {
        float* myl = s_top + (row * 32 + t) * 8;
#pragma unroll
        for (int q = 0; q < 8; q++) myl[q] = t8[q];
    }
    __syncwarp();
    // merge-tree 32 -> 1 sorted lists (within one warp)
#pragma unroll
    for (int L = 16; L >= 1; L >>= 1) {
        if (t < L) {
            float* A  = s_top + (row * 32 + t) * 8;
            float* B2 = s_top + (row * 32 + t + L) * 8;
            float out[8];
            int ia = 0, ib = 0;
#pragma unroll
            for (int r2 = 0; r2 < 8; r2++) {
                float va = A[ia];
                float vb = B2[ib];
                bool ta = (va >= vb);
                out[r2] = ta ? va : vb;
                ia += ta ? 1 : 0;
                ib += ta ? 0 : 1;
            }
#pragma unroll
            for (int r2 = 0; r2 < 8; r2++) A[r2] = out[r2];
        }
        __syncwarp();
    }
    const float thr = s_top[row * 256 + 7];
    const float mx  = s_top[row * 256 + 0];

    // ---- exp-sum over kept + union flags ----
    float psum = 0.f;
    for (int j = t; j < nv; j += 32) {
        float v = rd[j];
        if (v >= thr) { psum += __expf(v - mx); s_flag[j] = 1; }
    }
#pragma unroll
    for (int off = 16; off >= 1; off >>= 1)
        psum += __shfl_down_sync(0xffffffffu, psum, off);
    psum = __shfl_sync(0xffffffffu, psum, 0);
    const float inv = 1.f / psum;

    // ---- normalize in place ----
    {
        float* wrow = s_d + row * JTOT;
        for (int j = t; j < nv; j += 32) {
            float v = wrow[j];
            wrow[j] = (v >= thr) ? __expf(v - mx) * inv : 0.f;
        }
    }
    __syncthreads();

    // ---- survivor compaction: warp-shuffle prefix scan ----
    const int CH = 5;  // 512*5 >= 2064
    int base = tid * CH;
    int end = base + CH; if (end > nv) end = nv;
    int c = 0;
    for (int j = base; j < end; j++) c += s_flag[j];
    int val = c;
#pragma unroll
    for (int off = 1; off < 32; off <<= 1) {
        int u = __shfl_up_sync(0xffffffffu, val, off);
        if (t >= off) val += u;
    }
    if (t == 31) s_wsum[row] = val;
    __syncthreads();
    if (tid < 16) {
        int v = s_wsum[tid];
#pragma unroll
        for (int off = 1; off < 16; off <<= 1) {
            int u = __shfl_up_sync(0x0000ffffu, v, off);
            if (tid >= off) v += u;
        }
        s_wsum[tid] = v;
    }
    __syncthreads();
    {
        int pos = (row > 0 ? s_wsum[row - 1] : 0) + (val - c);
        for (int j = base; j < end; j++)
            if (s_flag[j]) s_list[pos++] = j;
    }
    const int cnt = s_wsum[15];
    __syncthreads();

    // ---- post-mix at survivor columns only ----
    for (int sI = tid; sI < cnt; sI += 512) {
        int j = s_list[sI];
        float a[16];
#pragma unroll
        for (int h2 = 0; h2 < 16; h2++) a[h2] = s_d[h2 * JTOT + j];
#pragma unroll
        for (int k = 0; k < 16; k++) {
            float acc2 = 0.f;
#pragma unroll
            for (int h2 = 0; h2 < 16; h2++) acc2 += a[h2] * s_post[h2 * 16 + k];
            s_d[k * JTOT + j] = acc2;
        }
    }
    __syncthreads();

    // ---- sparse attn2 @ V: thread owns (head k=warp, 2 dims) ----
    const int kk2 = tid >> 5;
    const int d2 = (tid & 31) << 1;
    float ax = 0.f, ay = 0.f;
    const float* Vb = &g_V[b][kk2][0][0];
    const float* wr = s_d + kk2 * JTOT;
    int s2 = 0;
    for (; s2 + 1 < cnt; s2 += 2) {
        int ja = s_list[s2], jb = s_list[s2 + 1];
        float wa = wr[ja], wb = wr[jb];
        float2 va = *(const float2*)(Vb + ja * 64 + d2);
        float2 vb = *(const float2*)(Vb + jb * 64 + d2);
        ax += wa * va.x + wb * vb.x;
        ay += wa * va.y + wb * vb.y;
    }
    if (s2 < cnt) {
        int ja = s_list[s2];
        float wa = wr[ja];
        float2 va = *(const float2*)(Vb + ja * 64 + d2);
        ax += wa * va.x; ay += wa * va.y;
    }
    *(float2*)&g_ctx[b][i][kk2 * 64 + d2] = make_float2(ax, ay);
}

// ============ output projection 128x128x16 + bias ============
__global__ __launch_bounds__(256, 2) void out_gemm_kernel(
    const float* __restrict__ Wo, const float* __restrict__ bo, float* __restrict__ out) {
    const float* A = &g_ctx[0][0][0];
    __shared__ float As[16][132];
    __shared__ float Bs[16][132];
    const int m0 = blockIdx.y << 7;
    const int n0 = blockIdx.x << 7;
    const int tid = threadIdx.x;
    const int ty = tid >> 4, tx = tid & 15;
    const int arow = tid >> 2, acol = (tid & 3) << 2;
    const int brow = tid >> 5, bcol = (tid & 31) << 2;
    float acc[8][8];
#pragma unroll
    for (int i = 0; i < 8; i++)
#pragma unroll
        for (int j = 0; j < 8; j++) acc[i][j] = 0.f;

    for (int k0 = 0; k0 < DIM; k0 += 16) {
        float4 a0 = *(const float4*)&A[(m0 + arow) * DIM + k0 + acol];
        float4 a1 = *(const float4*)&A[(m0 + arow + 64) * DIM + k0 + acol];
        float4 b0 = *(const float4*)&Wo[(k0 + brow) * DIM + n0 + bcol];
        float4 b1 = *(const float4*)&Wo[(k0 + brow + 8) * DIM + n0 + bcol];
        __syncthreads();
        As[acol + 0][arow] = a0.x; As[acol + 1][arow] = a0.y;
        As[acol + 2][arow] = a0.z; As[acol + 3][arow] = a0.w;
        As[acol + 0][arow + 64] = a1.x; As[acol + 1][arow + 64] = a1.y;
        As[acol + 2][arow + 64] = a1.z; As[acol + 3][arow + 64] = a1.w;
        *(float4*)&Bs[brow][bcol] = b0;
        *(float4*)&Bs[brow + 8][bcol] = b1;
        __syncthreads();
#pragma unroll
        for (int kk = 0; kk < 16; kk++) {
            float4 a04 = *(const float4*)&As[kk][ty << 3];
            float4 a14 = *(const float4*)&As[kk][(ty << 3) + 4];
            float4 b04 = *(const float4*)&Bs[kk][tx << 3];
            float4 b14 = *(const float4*)&Bs[kk][(tx << 3) + 4];
            float av[8] = {a04.x, a04.y, a04.z, a04.w, a14.x, a14.y, a14.z, a14.w};
            float bv[8] = {b04.x, b04.y, b04.z, b04.w, b14.x, b14.y, b14.z, b14.w};
#pragma unroll
            for (int i = 0; i < 8; i++)
#pragma unroll
                for (int j = 0; j < 8; j++) acc[i][j] += av[i] * bv[j];
        }
    }
#pragma unroll
    for (int i = 0; i < 8; i++) {
        int m = m0 + (ty << 3) + i;
#pragma unroll
        for (int j2 = 0; j2 < 8; j2 += 4) {
            int c = n0 + (tx << 3) + j2;
            float4 bias = *(const float4*)&bo[c];
            float4 v = make_float4(acc[i][j2] + bias.x, acc[i][j2 + 1] + bias.y,
                                   acc[i][j2 + 2] + bias.z, acc[i][j2 + 3] + bias.w);
            *(float4*)&out[m * DIM + c] = v;
        }
    }
}

// ---------------- launch ----------------
extern "C" void kernel_launch(void* const* d_in, const int* in_sizes, int n_in,
                              void* d_out, int out_size) {
    const float* x    = (const float*)d_in[0];
    const float* Wq   = (const float*)d_in[1];
    const float* Wk   = (const float*)d_in[2];
    const float* Wv   = (const float*)d_in[3];
    const float* pre  = (const float*)d_in[4];
    const float* post = (const float*)d_in[5];
    const float* mk   = (const float*)d_in[6];
    const float* mv   = (const float*)d_in[7];
    const float* Wo   = (const float*)d_in[8];
    const float* bo   = (const float*)d_in[9];
    float* out = (float*)d_out;

    cudaFuncSetAttribute(attn_kernel, cudaFuncAttributeMaxDynamicSharedMemorySize, ATTN_SMEM_BYTES);

    memfill_kernel<<<(BATCH * H * NM * DH + 255) / 256, 256>>>(mk, mv);
    gemm_qkv_kernel<<<dim3(DIM / 128, MROWS / 128, 3), 256>>>(x, Wq, Wk, Wv);
    dots_kernel<<<dim3((JTOT + 127) / 128, NSEQ / 128, BATCH * H), 256>>>();
    attn_kernel<<<dim3(NSEQ, BATCH), 512, ATTN_SMEM_BYTES>>>(pre, post);
    out_gemm_kernel<<<dim3(DIM / 128, MROWS / 128), 256>>>(Wo, bo, out);
}

// round 8
// speedup vs baseline: 1.2344x; 1.0318x over previous
#include <cuda_runtime.h>
#include <float.h>
#include <math.h>

#define BATCH 2
#define NSEQ  2048
#define DIM   1024
#define H     16
#define DH    64
#define NM    16
#define JTOT  2064          // NM + NSEQ
#define MROWS (BATCH*NSEQ)  // 4096

// ---------------- global scratch ----------------
__device__ float g_Q[BATCH][H][NSEQ][DH];
__device__ float g_K[BATCH][H][JTOT][DH];
__device__ float g_V[BATCH][H][JTOT][DH];
__device__ float g_dots[BATCH][H][NSEQ][JTOT];
__device__ float g_ctx[BATCH][NSEQ][H*DH];

// ---------------- fill mem_k / mem_v into K/V prefix ----------------
__global__ void memfill_kernel(const float* __restrict__ mk, const float* __restrict__ mv) {
    int idx = blockIdx.x * 256 + threadIdx.x;
    if (idx >= BATCH * H * NM * DH) return;
    int d = idx & 63;
    int j = (idx >> 6) & 15;
    int h = (idx >> 10) & 15;
    int b = idx >> 14;
    g_K[b][h][j][d] = mk[(h * NM + j) * DH + d];
    g_V[b][h][j][d] = mv[(h * NM + j) * DH + d];
}

// ============ 128x128x16 fp32 GEMM: QKV projection (bit-identical to R4) ============
__global__ __launch_bounds__(256, 2) void gemm_qkv_kernel(
    const float* __restrict__ x, const float* __restrict__ Wq,
    const float* __restrict__ Wk, const float* __restrict__ Wv) {
    const int z = blockIdx.z;
    const float* W = (z == 0) ? Wq : (z == 1) ? Wk : Wv;
    __shared__ float As[16][132];
    __shared__ float Bs[16][132];
    const int m0 = blockIdx.y << 7;
    const int n0 = blockIdx.x << 7;
    const int tid = threadIdx.x;
    const int ty = tid >> 4, tx = tid & 15;
    const int arow = tid >> 2, acol = (tid & 3) << 2;
    const int brow = tid >> 5, bcol = (tid & 31) << 2;
    float acc[8][8];
#pragma unroll
    for (int i = 0; i < 8; i++)
#pragma unroll
        for (int j = 0; j < 8; j++) acc[i][j] = 0.f;

    for (int k0 = 0; k0 < DIM; k0 += 16) {
        float4 a0 = *(const float4*)&x[(m0 + arow) * DIM + k0 + acol];
        float4 a1 = *(const float4*)&x[(m0 + arow + 64) * DIM + k0 + acol];
        float4 b0 = *(const float4*)&W[(k0 + brow) * DIM + n0 + bcol];
        float4 b1 = *(const float4*)&W[(k0 + brow + 8) * DIM + n0 + bcol];
        __syncthreads();
        As[acol + 0][arow] = a0.x; As[acol + 1][arow] = a0.y;
        As[acol + 2][arow] = a0.z; As[acol + 3][arow] = a0.w;
        As[acol + 0][arow + 64] = a1.x; As[acol + 1][arow + 64] = a1.y;
        As[acol + 2][arow + 64] = a1.z; As[acol + 3][arow + 64] = a1.w;
        *(float4*)&Bs[brow][bcol] = b0;
        *(float4*)&Bs[brow + 8][bcol] = b1;
        __syncthreads();
#pragma unroll
        for (int kk = 0; kk < 16; kk++) {
            float4 a04 = *(const float4*)&As[kk][ty << 3];
            float4 a14 = *(const float4*)&As[kk][(ty << 3) + 4];
            float4 b04 = *(const float4*)&Bs[kk][tx << 3];
            float4 b14 = *(const float4*)&Bs[kk][(tx << 3) + 4];
            float av[8] = {a04.x, a04.y, a04.z, a04.w, a14.x, a14.y, a14.z, a14.w};
            float bv[8] = {b04.x, b04.y, b04.z, b04.w, b14.x, b14.y, b14.z, b14.w};
#pragma unroll
            for (int i = 0; i < 8; i++)
#pragma unroll
                for (int j = 0; j < 8; j++) acc[i][j] += av[i] * bv[j];
        }
    }
#pragma unroll
    for (int i = 0; i < 8; i++) {
        int m = m0 + (ty << 3) + i;
        int b = m >> 11;
        int irow = m & 2047;
#pragma unroll
        for (int j2 = 0; j2 < 8; j2 += 4) {
            int c = n0 + (tx << 3) + j2;
            int h = c >> 6;
            int d = c & 63;
            float4 v = make_float4(acc[i][j2], acc[i][j2 + 1], acc[i][j2 + 2], acc[i][j2 + 3]);
            if (z == 0)      *(float4*)&g_Q[b][h][irow][d] = v;
            else if (z == 1) *(float4*)&g_K[b][h][NM + irow][d] = v;
            else             *(float4*)&g_V[b][h][NM + irow][d] = v;
        }
    }
}

// ============ dots: per (b,h) 128x128x64 tiles, causal skip (bit-identical to R4) ============
__global__ __launch_bounds__(256, 2) void dots_kernel() {
    const int bh = blockIdx.z;
    const int b = bh >> 4, h = bh & 15;
    const int i0 = blockIdx.y << 7;
    const int j0 = blockIdx.x << 7;
    if (j0 > i0 + 127 + NM) return;
    __shared__ float Qs[64][132];
    __shared__ float Ks[64][132];
    const int tid = threadIdx.x;
    const int ty = tid >> 4, tx = tid & 15;
    const int lr = tid >> 4;
    const int lc = (tid & 15) << 2;
#pragma unroll
    for (int rr = 0; rr < 128; rr += 16) {
        int r = lr + rr;
        float4 q = *(const float4*)&g_Q[b][h][i0 + r][lc];
        Qs[lc + 0][r] = q.x; Qs[lc + 1][r] = q.y;
        Qs[lc + 2][r] = q.z; Qs[lc + 3][r] = q.w;
        int j = j0 + r;
        float4 kv = make_float4(0.f, 0.f, 0.f, 0.f);
        if (j < JTOT) kv = *(const float4*)&g_K[b][h][j][lc];
        Ks[lc + 0][r] = kv.x; Ks[lc + 1][r] = kv.y;
        Ks[lc + 2][r] = kv.z; Ks[lc + 3][r] = kv.w;
    }
    __syncthreads();
    float acc[8][8];
#pragma unroll
    for (int i = 0; i < 8; i++)
#pragma unroll
        for (int j = 0; j < 8; j++) acc[i][j] = 0.f;
#pragma unroll
    for (int kk = 0; kk < 64; kk++) {
        float4 a04 = *(const float4*)&Qs[kk][ty << 3];
        float4 a14 = *(const float4*)&Qs[kk][(ty << 3) + 4];
        float4 b04 = *(const float4*)&Ks[kk][tx << 3];
        float4 b14 = *(const float4*)&Ks[kk][(tx << 3) + 4];
        float av[8] = {a04.x, a04.y, a04.z, a04.w, a14.x, a14.y, a14.z, a14.w};
        float bv[8] = {b04.x, b04.y, b04.z, b04.w, b14.x, b14.y, b14.z, b14.w};
#pragma unroll
        for (int i = 0; i < 8; i++)
#pragma unroll
            for (int j = 0; j < 8; j++) acc[i][j] += av[i] * bv[j];
    }
    const float scale = 0.125f;
#pragma unroll
    for (int i = 0; i < 8; i++) {
        int irow = i0 + (ty << 3) + i;
#pragma unroll
        for (int j2 = 0; j2 < 8; j2 += 4) {
            int jcol = j0 + (tx << 3) + j2;
            if (jcol < JTOT) {
                float4 v = make_float4(acc[i][j2] * scale, acc[i][j2 + 1] * scale,
                                       acc[i][j2 + 2] * scale, acc[i][j2 + 3] * scale);
                *(float4*)&g_dots[b][h][irow][jcol] = v;
            }
        }
    }
}

// ============ fused per-row attention: 1024 threads (32 warps), 2 warps per head-row ============
#define ATTN_SMEM_FLOATS (H*JTOT + 256 + 256 + H*64*8 + 32 + 32)
#define ATTN_SMEM_INTS   (JTOT + JTOT)
#define ATTN_SMEM_BYTES  ((ATTN_SMEM_FLOATS + ATTN_SMEM_INTS) * 4)

__global__ __launch_bounds__(1024) void attn_kernel(
    const float* __restrict__ pre, const float* __restrict__ post) {
    const int i = blockIdx.x;
    const int b = blockIdx.y;
    const int tid = threadIdx.x;
    extern __shared__ float sm[];
    float* s_d    = sm;                    // [16][2064] scores -> attn -> attn2
    float* s_pre  = s_d + H * JTOT;        // [16][16]
    float* s_post = s_pre + 256;           // [16][16]
    float* s_top  = s_post + 256;          // [16 rows][64 lists][8]
    float* s_zred = s_top + H * 64 * 8;    // [32] (2 partials per row)
    float* s_pad  = s_zred + 32;           // [32] spare
    int* s_flag = (int*)(s_pad + 32);      // [2064]
    int* s_list = s_flag + JTOT;           // [2064]
    __shared__ int s_wsum[32];

    if (tid < 256) { s_pre[tid] = pre[tid]; s_post[tid] = post[tid]; }
    const int nv = i + NM + 1;  // valid j: [0, nv)

    // ---- load raw dots, float4 main + scalar tail ----
    {
        const int n4 = nv >> 2;
        for (int h = 0; h < H; h++) {
            const float* src = &g_dots[b][h][i][0];
            float* dst = s_d + h * JTOT;
            for (int j = tid; j < n4; j += 1024)
                *(float4*)&dst[j << 2] = *(const float4*)&src[j << 2];
            int jt = (n4 << 2) + tid;
            if (jt < nv) dst[jt] = src[jt];
        }
    }
    for (int j = tid; j < JTOT; j += 1024) s_flag[j] = 0;
    __syncthreads();

    // ---- premix across heads + causal fill (identical arithmetic order to R4) ----
    for (int j = tid; j < JTOT; j += 1024) {
        if (j < nv) {
            float r[16];
#pragma unroll
            for (int h2 = 0; h2 < 16; h2++) r[h2] = s_d[h2 * JTOT + j];
#pragma unroll
            for (int k = 0; k < 16; k++) {
                float a = 0.f;
#pragma unroll
                for (int h2 = 0; h2 < 16; h2++) a += r[h2] * s_pre[h2 * 16 + k];
                s_d[k * JTOT + j] = a;
            }
        } else {
#pragma unroll
            for (int k = 0; k < 16; k++) s_d[k * JTOT + j] = -FLT_MAX;
        }
    }
    __syncthreads();

    // ---- top-8 per row: 64 threads (2 warps) per row ----
    const int row = tid >> 6;       // head-row 0..15
    const int t64 = tid & 63;       // thread within row group
    const float* rd = s_d + row * JTOT;
    float t8[8];
#pragma unroll
    for (int q = 0; q < 8; q++) t8[q] = -FLT_MAX;
    for (int j = t64; j < nv; j += 64) {
        float v = rd[j];
        if (v > t8[7]) {
            t8[7] = v;
#pragma unroll
            for (int q = 7; q >= 1; q--) {
                if (t8[q] > t8[q - 1]) { float tmp = t8[q]; t8[q] = t8[q - 1]; t8[q - 1] = tmp; }
            }
        }
    }
    {
        float* myl = s_top + (row * 64 + t64) * 8;
#pragma unroll
        for (int q = 0; q < 8; q++) myl[q] = t8[q];
    }
    __syncthreads();
    // merge-tree: 64 sorted lists -> 1 per row (block barriers; exact value merges)
#pragma unroll
    for (int L = 32; L >= 1; L >>= 1) {
        if (t64 < L) {
            float* A  = s_top + (row * 64 + t64) * 8;
            float* B2 = s_top + (row * 64 + t64 + L) * 8;
            float out[8];
            int ia = 0, ib = 0;
#pragma unroll
            for (int r2 = 0; r2 < 8; r2++) {
                float va = A[ia];
                float vb = B2[ib];
                bool ta = (va >= vb);
                out[r2] = ta ? va : vb;
                ia += ta ? 1 : 0;
                ib += ta ? 0 : 1;
            }
#pragma unroll
            for (int r2 = 0; r2 < 8; r2++) A[r2] = out[r2];
        }
        __syncthreads();
    }
    const float thr = s_top[row * 512 + 7];
    const float mx  = s_top[row * 512 + 0];

    // ---- exp-sum over kept + union flags (2 warps per row) ----
    float psum = 0.f;
    for (int j = t64; j < nv; j += 64) {
        float v = rd[j];
        if (v >= thr) { psum += __expf(v - mx); s_flag[j] = 1; }
    }
#pragma unroll
    for (int off = 16; off >= 1; off >>= 1)
        psum += __shfl_down_sync(0xffffffffu, psum, off);
    if ((tid & 31) == 0) s_zred[(tid >> 5)] = psum;   // warp slot = tid>>5 (2 per row)
    __syncthreads();
    const float Z = s_zred[row * 2] + s_zred[row * 2 + 1];
    const float inv = 1.f / Z;

    // ---- normalize in place ----
    {
        float* wrow = s_d + row * JTOT;
        for (int j = t64; j < nv; j += 64) {
            float v = wrow[j];
            wrow[j] = (v >= thr) ? __expf(v - mx) * inv : 0.f;
        }
    }
    __syncthreads();

    // ---- survivor compaction: 1024-thread two-level scan ----
    const int lane = tid & 31;
    const int wid  = tid >> 5;
    const int CH = 3;  // 1024*3 >= 2064
    int base = tid * CH;
    int end = base + CH; if (end > nv) end = nv;
    int c = 0;
    for (int j = base; j < end; j++) c += s_flag[j];
    int val = c;
#pragma unroll
    for (int off = 1; off < 32; off <<= 1) {
        int u = __shfl_up_sync(0xffffffffu, val, off);
        if (lane >= off) val += u;
    }
    if (lane == 31) s_wsum[wid] = val;
    __syncthreads();
    if (tid < 32) {
        int v = s_wsum[tid];
#pragma unroll
        for (int off = 1; off < 32; off <<= 1) {
            int u = __shfl_up_sync(0xffffffffu, v, off);
            if (tid >= off) v += u;
        }
        s_wsum[tid] = v;
    }
    __syncthreads();
    {
        int pos = (wid > 0 ? s_wsum[wid - 1] : 0) + (val - c);
        for (int j = base; j < end; j++)
            if (s_flag[j]) s_list[pos++] = j;
    }
    const int cnt = s_wsum[31];
    __syncthreads();

    // ---- post-mix at survivor columns only ----
    for (int sI = tid; sI < cnt; sI += 1024) {
        int j = s_list[sI];
        float a[16];
#pragma unroll
        for (int h2 = 0; h2 < 16; h2++) a[h2] = s_d[h2 * JTOT + j];
#pragma unroll
        for (int k = 0; k < 16; k++) {
            float acc2 = 0.f;
#pragma unroll
            for (int h2 = 0; h2 < 16; h2++) acc2 += a[h2] * s_post[h2 * 16 + k];
            s_d[k * JTOT + j] = acc2;
        }
    }
    __syncthreads();

    // ---- sparse attn2 @ V: 64 threads per head, 1 dim each ----
    const int kk2 = tid >> 6;   // head
    const int d = tid & 63;     // dim
    float acc = 0.f;
    const float* Vb = &g_V[b][kk2][0][0];
    const float* wr = s_d + kk2 * JTOT;
    int s2 = 0;
    for (; s2 + 1 < cnt; s2 += 2) {
        int ja = s_list[s2], jb = s_list[s2 + 1];
        float wa = wr[ja], wb = wr[jb];
        acc += wa * Vb[ja * 64 + d] + wb * Vb[jb * 64 + d];
    }
    if (s2 < cnt) {
        int ja = s_list[s2];
        acc += wr[ja] * Vb[ja * 64 + d];
    }
    g_ctx[b][i][kk2 * 64 + d] = acc;
}

// ============ output projection 128x128x16 + bias (bit-identical to R4) ============
__global__ __launch_bounds__(256, 2) void out_gemm_kernel(
    const float* __restrict__ Wo, const float* __restrict__ bo, float* __restrict__ out) {
    const float* A = &g_ctx[0][0][0];
    __shared__ float As[16][132];
    __shared__ float Bs[16][132];
    const int m0 = blockIdx.y << 7;
    const int n0 = blockIdx.x << 7;
    const int tid = threadIdx.x;
    const int ty = tid >> 4, tx = tid & 15;
    const int arow = tid >> 2, acol = (tid & 3) << 2;
    const int brow = tid >> 5, bcol = (tid & 31) << 2;
    float acc[8][8];
#pragma unroll
    for (int i = 0; i < 8; i++)
#pragma unroll
        for (int j = 0; j < 8; j++) acc[i][j] = 0.f;

    for (int k0 = 0; k0 < DIM; k0 += 16) {
        float4 a0 = *(const float4*)&A[(m0 + arow) * DIM + k0 + acol];
        float4 a1 = *(const float4*)&A[(m0 + arow + 64) * DIM + k0 + acol];
        float4 b0 = *(const float4*)&Wo[(k0 + brow) * DIM + n0 + bcol];
        float4 b1 = *(const float4*)&Wo[(k0 + brow + 8) * DIM + n0 + bcol];
        __syncthreads();
        As[acol + 0][arow] = a0.x; As[acol + 1][arow] = a0.y;
        As[acol + 2][arow] = a0.z; As[acol + 3][arow] = a0.w;
        As[acol + 0][arow + 64] = a1.x; As[acol + 1][arow + 64] = a1.y;
        As[acol + 2][arow + 64] = a1.z; As[acol + 3][arow + 64] = a1.w;
        *(float4*)&Bs[brow][bcol] = b0;
        *(float4*)&Bs[brow + 8][bcol] = b1;
        __syncthreads();
#pragma unroll
        for (int kk = 0; kk < 16; kk++) {
            float4 a04 = *(const float4*)&As[kk][ty << 3];
            float4 a14 = *(const float4*)&As[kk][(ty << 3) + 4];
            float4 b04 = *(const float4*)&Bs[kk][tx << 3];
            float4 b14 = *(const float4*)&Bs[kk][(tx << 3) + 4];
            float av[8] = {a04.x, a04.y, a04.z, a04.w, a14.x, a14.y, a14.z, a14.w};
            float bv[8] = {b04.x, b04.y, b04.z, b04.w, b14.x, b14.y, b14.z, b14.w};
#pragma unroll
            for (int i = 0; i < 8; i++)
#pragma unroll
                for (int j = 0; j < 8; j++) acc[i][j] += av[i] * bv[j];
        }
    }
#pragma unroll
    for (int i = 0; i < 8; i++) {
        int m = m0 + (ty << 3) + i;
#pragma unroll
        for (int j2 = 0; j2 < 8; j2 += 4) {
            int c = n0 + (tx << 3) + j2;
            float4 bias = *(const float4*)&bo[c];
            float4 v = make_float4(acc[i][j2] + bias.x, acc[i][j2 + 1] + bias.y,
                                   acc[i][j2 + 2] + bias.z, acc[i][j2 + 3] + bias.w);
            *(float4*)&out[m * DIM + c] = v;
        }
    }
}

// ---------------- launch ----------------
extern "C" void kernel_launch(void* const* d_in, const int* in_sizes, int n_in,
                              void* d_out, int out_size) {
    const float* x    = (const float*)d_in[0];
    const float* Wq   = (const float*)d_in[1];
    const float* Wk   = (const float*)d_in[2];
    const float* Wv   = (const float*)d_in[3];
    const float* pre  = (const float*)d_in[4];
    const float* post = (const float*)d_in[5];
    const float* mk   = (const float*)d_in[6];
    const float* mv   = (const float*)d_in[7];
    const float* Wo   = (const float*)d_in[8];
    const float* bo   = (const float*)d_in[9];
    float* out = (float*)d_out;

    cudaFuncSetAttribute(attn_kernel, cudaFuncAttributeMaxDynamicSharedMemorySize, ATTN_SMEM_BYTES);

    memfill_kernel<<<(BATCH * H * NM * DH + 255) / 256, 256>>>(mk, mv);
    gemm_qkv_kernel<<<dim3(DIM / 128, MROWS / 128, 3), 256>>>(x, Wq, Wk, Wv);
    dots_kernel<<<dim3((JTOT + 127) / 128, NSEQ / 128, BATCH * H), 256>>>();
    attn_kernel<<<dim3(NSEQ, BATCH), 1024, ATTN_SMEM_BYTES>>>(pre, post);
    out_gemm_kernel<<<dim3(DIM / 128, MROWS / 128), 256>>>(Wo, bo, out);
}

// round 9
// speedup vs baseline: 1.5302x; 1.2396x over previous
#include <cuda_runtime.h>
#include <float.h>
#include <math.h>

#define BATCH 2
#define NSEQ  2048
#define DIM   1024
#define H     16
#define DH    64
#define NM    16
#define JTOT  2064          // NM + NSEQ
#define MROWS (BATCH*NSEQ)  // 4096

// ---------------- global scratch ----------------
__device__ float g_Q[BATCH][H][NSEQ][DH];
__device__ float g_K[BATCH][H][JTOT][DH];
__device__ float g_V[BATCH][H][JTOT][DH];
__device__ float g_dots[BATCH][H][NSEQ][JTOT];
__device__ float g_ctx[BATCH][NSEQ][H*DH];

// ---------------- fill mem_k / mem_v into K/V prefix ----------------
__global__ void memfill_kernel(const float* __restrict__ mk, const float* __restrict__ mv) {
    int idx = blockIdx.x * 256 + threadIdx.x;
    if (idx >= BATCH * H * NM * DH) return;
    int d = idx & 63;
    int j = (idx >> 6) & 15;
    int h = (idx >> 10) & 15;
    int b = idx >> 14;
    g_K[b][h][j][d] = mk[(h * NM + j) * DH + d];
    g_V[b][h][j][d] = mv[(h * NM + j) * DH + d];
}

// ============ 128x128x16 fp32 GEMM: QKV projection (bit-identical) ============
__global__ __launch_bounds__(256, 2) void gemm_qkv_kernel(
    const float* __restrict__ x, const float* __restrict__ Wq,
    const float* __restrict__ Wk, const float* __restrict__ Wv) {
    const int z = blockIdx.z;
    const float* W = (z == 0) ? Wq : (z == 1) ? Wk : Wv;
    __shared__ float As[16][132];
    __shared__ float Bs[16][132];
    const int m0 = blockIdx.y << 7;
    const int n0 = blockIdx.x << 7;
    const int tid = threadIdx.x;
    const int ty = tid >> 4, tx = tid & 15;
    const int arow = tid >> 2, acol = (tid & 3) << 2;
    const int brow = tid >> 5, bcol = (tid & 31) << 2;
    float acc[8][8];
#pragma unroll
    for (int i = 0; i < 8; i++)
#pragma unroll
        for (int j = 0; j < 8; j++) acc[i][j] = 0.f;

    for (int k0 = 0; k0 < DIM; k0 += 16) {
        float4 a0 = *(const float4*)&x[(m0 + arow) * DIM + k0 + acol];
        float4 a1 = *(const float4*)&x[(m0 + arow + 64) * DIM + k0 + acol];
        float4 b0 = *(const float4*)&W[(k0 + brow) * DIM + n0 + bcol];
        float4 b1 = *(const float4*)&W[(k0 + brow + 8) * DIM + n0 + bcol];
        __syncthreads();
        As[acol + 0][arow] = a0.x; As[acol + 1][arow] = a0.y;
        As[acol + 2][arow] = a0.z; As[acol + 3][arow] = a0.w;
        As[acol + 0][arow + 64] = a1.x; As[acol + 1][arow + 64] = a1.y;
        As[acol + 2][arow + 64] = a1.z; As[acol + 3][arow + 64] = a1.w;
        *(float4*)&Bs[brow][bcol] = b0;
        *(float4*)&Bs[brow + 8][bcol] = b1;
        __syncthreads();
#pragma unroll
        for (int kk = 0; kk < 16; kk++) {
            float4 a04 = *(const float4*)&As[kk][ty << 3];
            float4 a14 = *(const float4*)&As[kk][(ty << 3) + 4];
            float4 b04 = *(const float4*)&Bs[kk][tx << 3];
            float4 b14 = *(const float4*)&Bs[kk][(tx << 3) + 4];
            float av[8] = {a04.x, a04.y, a04.z, a04.w, a14.x, a14.y, a14.z, a14.w};
            float bv[8] = {b04.x, b04.y, b04.z, b04.w, b14.x, b14.y, b14.z, b14.w};
#pragma unroll
            for (int i = 0; i < 8; i++)
#pragma unroll
                for (int j = 0; j < 8; j++) acc[i][j] += av[i] * bv[j];
        }
    }
#pragma unroll
    for (int i = 0; i < 8; i++) {
        int m = m0 + (ty << 3) + i;
        int b = m >> 11;
        int irow = m & 2047;
#pragma unroll
        for (int j2 = 0; j2 < 8; j2 += 4) {
            int c = n0 + (tx << 3) + j2;
            int h = c >> 6;
            int d = c & 63;
            float4 v = make_float4(acc[i][j2], acc[i][j2 + 1], acc[i][j2 + 2], acc[i][j2 + 3]);
            if (z == 0)      *(float4*)&g_Q[b][h][irow][d] = v;
            else if (z == 1) *(float4*)&g_K[b][h][NM + irow][d] = v;
            else             *(float4*)&g_V[b][h][NM + irow][d] = v;
        }
    }
}

// ============ dots: per (b,h) 128x128x64 tiles, causal skip (bit-identical) ============
__global__ __launch_bounds__(256, 2) void dots_kernel() {
    const int bh = blockIdx.z;
    const int b = bh >> 4, h = bh & 15;
    const int i0 = blockIdx.y << 7;
    const int j0 = blockIdx.x << 7;
    if (j0 > i0 + 127 + NM) return;
    __shared__ float Qs[64][132];
    __shared__ float Ks[64][132];
    const int tid = threadIdx.x;
    const int ty = tid >> 4, tx = tid & 15;
    const int lr = tid >> 4;
    const int lc = (tid & 15) << 2;
#pragma unroll
    for (int rr = 0; rr < 128; rr += 16) {
        int r = lr + rr;
        float4 q = *(const float4*)&g_Q[b][h][i0 + r][lc];
        Qs[lc + 0][r] = q.x; Qs[lc + 1][r] = q.y;
        Qs[lc + 2][r] = q.z; Qs[lc + 3][r] = q.w;
        int j = j0 + r;
        float4 kv = make_float4(0.f, 0.f, 0.f, 0.f);
        if (j < JTOT) kv = *(const float4*)&g_K[b][h][j][lc];
        Ks[lc + 0][r] = kv.x; Ks[lc + 1][r] = kv.y;
        Ks[lc + 2][r] = kv.z; Ks[lc + 3][r] = kv.w;
    }
    __syncthreads();
    float acc[8][8];
#pragma unroll
    for (int i = 0; i < 8; i++)
#pragma unroll
        for (int j = 0; j < 8; j++) acc[i][j] = 0.f;
#pragma unroll
    for (int kk = 0; kk < 64; kk++) {
        float4 a04 = *(const float4*)&Qs[kk][ty << 3];
        float4 a14 = *(const float4*)&Qs[kk][(ty << 3) + 4];
        float4 b04 = *(const float4*)&Ks[kk][tx << 3];
        float4 b14 = *(const float4*)&Ks[kk][(tx << 3) + 4];
        float av[8] = {a04.x, a04.y, a04.z, a04.w, a14.x, a14.y, a14.z, a14.w};
        float bv[8] = {b04.x, b04.y, b04.z, b04.w, b14.x, b14.y, b14.z, b14.w};
#pragma unroll
        for (int i = 0; i < 8; i++)
#pragma unroll
            for (int j = 0; j < 8; j++) acc[i][j] += av[i] * bv[j];
    }
    const float scale = 0.125f;
#pragma unroll
    for (int i = 0; i < 8; i++) {
        int irow = i0 + (ty << 3) + i;
#pragma unroll
        for (int j2 = 0; j2 < 8; j2 += 4) {
            int jcol = j0 + (tx << 3) + j2;
            if (jcol < JTOT) {
                float4 v = make_float4(acc[i][j2] * scale, acc[i][j2 + 1] * scale,
                                       acc[i][j2 + 2] * scale, acc[i][j2 + 3] * scale);
                *(float4*)&g_dots[b][h][irow][jcol] = v;
            }
        }
    }
}

// ============ fused per-row attention: 1024 threads, streamlined passes ============
#define ATTN_SMEM_FLOATS (H*JTOT + 256 + 256 + H*64*8 + 32 + 16)
#define ATTN_SMEM_INTS   (JTOT + JTOT)
#define ATTN_SMEM_BYTES  ((ATTN_SMEM_FLOATS + ATTN_SMEM_INTS) * 4)

#define INS8(vv) do { float _v = (vv); \
    if (_v > t8[7]) { t8[7] = _v; \
        _Pragma("unroll") \
        for (int _q = 7; _q >= 1; _q--) \
            if (t8[_q] > t8[_q-1]) { float _t = t8[_q]; t8[_q] = t8[_q-1]; t8[_q-1] = _t; } \
    } } while (0)

__global__ __launch_bounds__(1024) void attn_kernel(
    const float* __restrict__ pre, const float* __restrict__ post) {
    const int i = (NSEQ - 1) - blockIdx.x;   // longest rows first
    const int b = blockIdx.y;
    const int tid = threadIdx.x;
    extern __shared__ float sm[];
    float* s_d    = sm;                    // [16][2064] premixed -> exp -> attn2
    float* s_pre  = s_d + H * JTOT;        // [16][16]
    float* s_post = s_pre + 256;           // [16][16]
    float* s_top  = s_post + 256;          // [16 rows][64 lists][8]
    float* s_zred = s_top + H * 64 * 8;    // [32]
    float* s_inv  = s_zred + 32;           // [16]
    int* s_flag = (int*)(s_inv + 16);      // [2064]
    int* s_list = s_flag + JTOT;           // [2064]
    __shared__ int s_wsum[32];

    if (tid < 256) { s_pre[tid] = pre[tid]; s_post[tid] = post[tid]; }
    const int nv = i + NM + 1;  // valid j: [0, nv)
    __syncthreads();

    // ---- fused load + premix + flag zero (reads g_dots directly) ----
    {
        const float* dbase = &g_dots[b][0][i][0];
        const long hstride = (long)NSEQ * JTOT;
        const int npair = (nv + 1) >> 1;
        for (int p = tid; p < npair; p += 1024) {
            int j = p << 1;
            s_flag[j] = 0;
            if (j + 1 < nv) {
                s_flag[j + 1] = 0;
                float2 r[16];
#pragma unroll
                for (int h2 = 0; h2 < 16; h2++)
                    r[h2] = *(const float2*)&dbase[h2 * hstride + j];
#pragma unroll
                for (int k = 0; k < 16; k++) {
                    float a0 = 0.f, a1 = 0.f;
#pragma unroll
                    for (int h2 = 0; h2 < 16; h2++) {
                        float w = s_pre[h2 * 16 + k];
                        a0 += r[h2].x * w;
                        a1 += r[h2].y * w;
                    }
                    *(float2*)&s_d[k * JTOT + j] = make_float2(a0, a1);
                }
            } else {
                float r1[16];
#pragma unroll
                for (int h2 = 0; h2 < 16; h2++) r1[h2] = dbase[h2 * hstride + j];
#pragma unroll
                for (int k = 0; k < 16; k++) {
                    float a = 0.f;
#pragma unroll
                    for (int h2 = 0; h2 < 16; h2++) a += r1[h2] * s_pre[h2 * 16 + k];
                    s_d[k * JTOT + j] = a;
                }
            }
        }
    }
    __syncthreads();

    // ---- top-8 per row: 64 threads per row, float4 scan ----
    const int row = tid >> 6;
    const int t64 = tid & 63;
    const float* rd = s_d + row * JTOT;
    float t8[8];
#pragma unroll
    for (int q = 0; q < 8; q++) t8[q] = -FLT_MAX;
    {
        const int n4 = nv >> 2;
        for (int q = t64; q < n4; q += 64) {
            float4 v4 = *(const float4*)&rd[q << 2];
            INS8(v4.x); INS8(v4.y); INS8(v4.z); INS8(v4.w);
        }
        int tail = nv & 3;
        if (t64 < tail) INS8(rd[(n4 << 2) + t64]);
    }
    {
        float* myl = s_top + (row * 64 + t64) * 8;
#pragma unroll
        for (int q = 0; q < 8; q++) myl[q] = t8[q];
    }
    __syncthreads();
    // merge-tree: 64 sorted lists -> 1 per row
#pragma unroll
    for (int L = 32; L >= 1; L >>= 1) {
        if (t64 < L) {
            float* A  = s_top + (row * 64 + t64) * 8;
            float* B2 = s_top + (row * 64 + t64 + L) * 8;
            float out[8];
            int ia = 0, ib = 0;
#pragma unroll
            for (int r2 = 0; r2 < 8; r2++) {
                float va = A[ia];
                float vb = B2[ib];
                bool ta = (va >= vb);
                out[r2] = ta ? va : vb;
                ia += ta ? 1 : 0;
                ib += ta ? 0 : 1;
            }
#pragma unroll
            for (int r2 = 0; r2 < 8; r2++) A[r2] = out[r2];
        }
        __syncthreads();
    }
    const float thr = s_top[row * 512 + 7];
    const float mx  = s_top[row * 512 + 0];

    // ---- exp-sum pass: write exp(v-mx) for kept, 0 otherwise; set union flags ----
    float psum = 0.f;
    {
        float* wrow = s_d + row * JTOT;
        const int np2 = nv >> 1;
        for (int q = t64; q < np2; q += 64) {
            int j = q << 1;
            float2 v = *(const float2*)&wrow[j];
            bool k0 = (v.x >= thr), k1 = (v.y >= thr);
            float e0 = k0 ? __expf(v.x - mx) : 0.f;
            float e1 = k1 ? __expf(v.y - mx) : 0.f;
            psum += e0; psum += e1;
            *(float2*)&wrow[j] = make_float2(e0, e1);
            if (k0) s_flag[j] = 1;
            if (k1) s_flag[j + 1] = 1;
        }
        if ((nv & 1) && t64 == 0) {
            int j = nv - 1;
            float v = wrow[j];
            if (v >= thr) { float e = __expf(v - mx); psum += e; wrow[j] = e; s_flag[j] = 1; }
            else wrow[j] = 0.f;
        }
    }
#pragma unroll
    for (int off = 16; off >= 1; off >>= 1)
        psum += __shfl_down_sync(0xffffffffu, psum, off);
    if ((tid & 31) == 0) s_zred[tid >> 5] = psum;
    __syncthreads();
    if (t64 == 0) s_inv[row] = 1.f / (s_zred[row * 2] + s_zred[row * 2 + 1]);

    // ---- survivor compaction: 1024-thread two-level scan ----
    const int lane = tid & 31;
    const int wid  = tid >> 5;
    const int CH = 3;  // 1024*3 >= 2064
    int base = tid * CH;
    int end = base + CH; if (end > nv) end = nv;
    int c = 0;
    for (int j = base; j < end; j++) c += s_flag[j];
    int val = c;
#pragma unroll
    for (int off = 1; off < 32; off <<= 1) {
        int u = __shfl_up_sync(0xffffffffu, val, off);
        if (lane >= off) val += u;
    }
    if (lane == 31) s_wsum[wid] = val;
    __syncthreads();
    if (tid < 32) {
        int v = s_wsum[tid];
#pragma unroll
        for (int off = 1; off < 32; off <<= 1) {
            int u = __shfl_up_sync(0xffffffffu, v, off);
            if (tid >= off) v += u;
        }
        s_wsum[tid] = v;
    }
    __syncthreads();
    {
        int pos = (wid > 0 ? s_wsum[wid - 1] : 0) + (val - c);
        for (int j = base; j < end; j++)
            if (s_flag[j]) s_list[pos++] = j;
    }
    const int cnt = s_wsum[31];
    __syncthreads();

    // ---- post-mix at survivor columns (inv folded in) ----
    for (int sI = tid; sI < cnt; sI += 1024) {
        int j = s_list[sI];
        float a[16];
#pragma unroll
        for (int h2 = 0; h2 < 16; h2++) a[h2] = s_d[h2 * JTOT + j] * s_inv[h2];
#pragma unroll
        for (int k = 0; k < 16; k++) {
            float acc2 = 0.f;
#pragma unroll
            for (int h2 = 0; h2 < 16; h2++) acc2 += a[h2] * s_post[h2 * 16 + k];
            s_d[k * JTOT + j] = acc2;
        }
    }
    __syncthreads();

    // ---- sparse attn2 @ V: 64 threads per head, 1 dim each ----
    const int kk2 = tid >> 6;   // head
    const int d = tid & 63;     // dim
    float acc = 0.f;
    const float* Vb = &g_V[b][kk2][0][0];
    const float* wr = s_d + kk2 * JTOT;
    int s2 = 0;
    for (; s2 + 1 < cnt; s2 += 2) {
        int ja = s_list[s2], jb = s_list[s2 + 1];
        float wa = wr[ja], wb = wr[jb];
        acc += wa * Vb[ja * 64 + d] + wb * Vb[jb * 64 + d];
    }
    if (s2 < cnt) {
        int ja = s_list[s2];
        acc += wr[ja] * Vb[ja * 64 + d];
    }
    g_ctx[b][i][kk2 * 64 + d] = acc;
}

// ============ output projection 128x128x16 + bias (bit-identical) ============
__global__ __launch_bounds__(256, 2) void out_gemm_kernel(
    const float* __restrict__ Wo, const float* __restrict__ bo, float* __restrict__ out) {
    const float* A = &g_ctx[0][0][0];
    __shared__ float As[16][132];
    __shared__ float Bs[16][132];
    const int m0 = blockIdx.y << 7;
    const int n0 = blockIdx.x << 7;
    const int tid = threadIdx.x;
    const int ty = tid >> 4, tx = tid & 15;
    const int arow = tid >> 2, acol = (tid & 3) << 2;
    const int brow = tid >> 5, bcol = (tid & 31) << 2;
    float acc[8][8];
#pragma unroll
    for (int i = 0; i < 8; i++)
#pragma unroll
        for (int j = 0; j < 8; j++) acc[i][j] = 0.f;

    for (int k0 = 0; k0 < DIM; k0 += 16) {
        float4 a0 = *(const float4*)&A[(m0 + arow) * DIM + k0 + acol];
        float4 a1 = *(const float4*)&A[(m0 + arow + 64) * DIM + k0 + acol];
        float4 b0 = *(const float4*)&Wo[(k0 + brow) * DIM + n0 + bcol];
        float4 b1 = *(const float4*)&Wo[(k0 + brow + 8) * DIM + n0 + bcol];
        __syncthreads();
        As[acol + 0][arow] = a0.x; As[acol + 1][arow] = a0.y;
        As[acol + 2][arow] = a0.z; As[acol + 3][arow] = a0.w;
        As[acol + 0][arow + 64] = a1.x; As[acol + 1][arow + 64] = a1.y;
        As[acol + 2][arow + 64] = a1.z; As[acol + 3][arow + 64] = a1.w;
        *(float4*)&Bs[brow][bcol] = b0;
        *(float4*)&Bs[brow + 8][bcol] = b1;
        __syncthreads();
#pragma unroll
        for (int kk = 0; kk < 16; kk++) {
            float4 a04 = *(const float4*)&As[kk][ty << 3];
            float4 a14 = *(const float4*)&As[kk][(ty << 3) + 4];
            float4 b04 = *(const float4*)&Bs[kk][tx << 3];
            float4 b14 = *(const float4*)&Bs[kk][(tx << 3) + 4];
            float av[8] = {a04.x, a04.y, a04.z, a04.w, a14.x, a14.y, a14.z, a14.w};
            float bv[8] = {b04.x, b04.y, b04.z, b04.w, b14.x, b14.y, b14.z, b14.w};
#pragma unroll
            for (int i = 0; i < 8; i++)
#pragma unroll
                for (int j = 0; j < 8; j++) acc[i][j] += av[i] * bv[j];
        }
    }
#pragma unroll
    for (int i = 0; i < 8; i++) {
        int m = m0 + (ty << 3) + i;
#pragma unroll
        for (int j2 = 0; j2 < 8; j2 += 4) {
            int c = n0 + (tx << 3) + j2;
            float4 bias = *(const float4*)&bo[c];
            float4 v = make_float4(acc[i][j2] + bias.x, acc[i][j2 + 1] + bias.y,
                                   acc[i][j2 + 2] + bias.z, acc[i][j2 + 3] + bias.w);
            *(float4*)&out[m * DIM + c] = v;
        }
    }
}

// ---------------- launch ----------------
extern "C" void kernel_launch(void* const* d_in, const int* in_sizes, int n_in,
                              void* d_out, int out_size) {
    const float* x    = (const float*)d_in[0];
    const float* Wq   = (const float*)d_in[1];
    const float* Wk   = (const float*)d_in[2];
    const float* Wv   = (const float*)d_in[3];
    const float* pre  = (const float*)d_in[4];
    const float* post = (const float*)d_in[5];
    const float* mk   = (const float*)d_in[6];
    const float* mv   = (const float*)d_in[7];
    const float* Wo   = (const float*)d_in[8];
    const float* bo   = (const float*)d_in[9];
    float* out = (float*)d_out;

    cudaFuncSetAttribute(attn_kernel, cudaFuncAttributeMaxDynamicSharedMemorySize, ATTN_SMEM_BYTES);

    memfill_kernel<<<(BATCH * H * NM * DH + 255) / 256, 256>>>(mk, mv);
    gemm_qkv_kernel<<<dim3(DIM / 128, MROWS / 128, 3), 256>>>(x, Wq, Wk, Wv);
    dots_kernel<<<dim3((JTOT + 127) / 128, NSEQ / 128, BATCH * H), 256>>>();
    attn_kernel<<<dim3(NSEQ, BATCH), 1024, ATTN_SMEM_BYTES>>>(pre, post);
    out_gemm_kernel<<<dim3(DIM / 128, MROWS / 128), 256>>>(Wo, bo, out);
}

// round 10
// speedup vs baseline: 1.5350x; 1.0031x over previous
#include <cuda_runtime.h>
#include <float.h>
#include <math.h>

#define BATCH 2
#define NSEQ  2048
#define DIM   1024
#define H     16
#define DH    64
#define NM    16
#define JTOT  2064          // NM + NSEQ
#define MROWS (BATCH*NSEQ)  // 4096

// ---------------- global scratch ----------------
__device__ float g_Q[BATCH][H][NSEQ][DH];
__device__ float g_K[BATCH][H][JTOT][DH];
__device__ float g_V[BATCH][H][JTOT][DH];
__device__ float g_dots[BATCH][H][NSEQ][JTOT];
__device__ float g_ctx[BATCH][NSEQ][H*DH];

// ---------------- fill mem_k / mem_v into K/V prefix ----------------
__global__ void memfill_kernel(const float* __restrict__ mk, const float* __restrict__ mv) {
    int idx = blockIdx.x * 256 + threadIdx.x;
    if (idx >= BATCH * H * NM * DH) return;
    int d = idx & 63;
    int j = (idx >> 6) & 15;
    int h = (idx >> 10) & 15;
    int b = idx >> 14;
    g_K[b][h][j][d] = mk[(h * NM + j) * DH + d];
    g_V[b][h][j][d] = mv[(h * NM + j) * DH + d];
}

// ============ 128x128x16 fp32 GEMM, double-buffered: QKV projection ============
__global__ __launch_bounds__(256, 2) void gemm_qkv_kernel(
    const float* __restrict__ x, const float* __restrict__ Wq,
    const float* __restrict__ Wk, const float* __restrict__ Wv) {
    const int z = blockIdx.z;
    const float* W = (z == 0) ? Wq : (z == 1) ? Wk : Wv;
    __shared__ float As[2][16][132];
    __shared__ float Bs[2][16][132];
    const int m0 = blockIdx.y << 7;
    const int n0 = blockIdx.x << 7;
    const int tid = threadIdx.x;
    const int ty = tid >> 4, tx = tid & 15;
    const int arow = tid >> 2, acol = (tid & 3) << 2;
    const int brow = tid >> 5, bcol = (tid & 31) << 2;
    float acc[8][8];
#pragma unroll
    for (int i = 0; i < 8; i++)
#pragma unroll
        for (int j = 0; j < 8; j++) acc[i][j] = 0.f;

    // prologue: load k0 = 0 into buffer 0
    {
        float4 a0 = *(const float4*)&x[(m0 + arow) * DIM + acol];
        float4 a1 = *(const float4*)&x[(m0 + arow + 64) * DIM + acol];
        float4 b0 = *(const float4*)&W[brow * DIM + n0 + bcol];
        float4 b1 = *(const float4*)&W[(brow + 8) * DIM + n0 + bcol];
        As[0][acol + 0][arow] = a0.x; As[0][acol + 1][arow] = a0.y;
        As[0][acol + 2][arow] = a0.z; As[0][acol + 3][arow] = a0.w;
        As[0][acol + 0][arow + 64] = a1.x; As[0][acol + 1][arow + 64] = a1.y;
        As[0][acol + 2][arow + 64] = a1.z; As[0][acol + 3][arow + 64] = a1.w;
        *(float4*)&Bs[0][brow][bcol] = b0;
        *(float4*)&Bs[0][brow + 8][bcol] = b1;
    }
    __syncthreads();

    int cur = 0;
    for (int k0 = 0; k0 < DIM; k0 += 16) {
        const int nxt = k0 + 16;
        float4 na0, na1, nb0, nb1;
        if (nxt < DIM) {
            na0 = *(const float4*)&x[(m0 + arow) * DIM + nxt + acol];
            na1 = *(const float4*)&x[(m0 + arow + 64) * DIM + nxt + acol];
            nb0 = *(const float4*)&W[(nxt + brow) * DIM + n0 + bcol];
            nb1 = *(const float4*)&W[(nxt + brow + 8) * DIM + n0 + bcol];
        }
#pragma unroll
        for (int kk = 0; kk < 16; kk++) {
            float4 a04 = *(const float4*)&As[cur][kk][ty << 3];
            float4 a14 = *(const float4*)&As[cur][kk][(ty << 3) + 4];
            float4 b04 = *(const float4*)&Bs[cur][kk][tx << 3];
            float4 b14 = *(const float4*)&Bs[cur][kk][(tx << 3) + 4];
            float av[8] = {a04.x, a04.y, a04.z, a04.w, a14.x, a14.y, a14.z, a14.w};
            float bv[8] = {b04.x, b04.y, b04.z, b04.w, b14.x, b14.y, b14.z, b14.w};
#pragma unroll
            for (int i = 0; i < 8; i++)
#pragma unroll
                for (int j = 0; j < 8; j++) acc[i][j] += av[i] * bv[j];
        }
        if (nxt < DIM) {
            const int nb = cur ^ 1;
            As[nb][acol + 0][arow] = na0.x; As[nb][acol + 1][arow] = na0.y;
            As[nb][acol + 2][arow] = na0.z; As[nb][acol + 3][arow] = na0.w;
            As[nb][acol + 0][arow + 64] = na1.x; As[nb][acol + 1][arow + 64] = na1.y;
            As[nb][acol + 2][arow + 64] = na1.z; As[nb][acol + 3][arow + 64] = na1.w;
            *(float4*)&Bs[nb][brow][bcol] = nb0;
            *(float4*)&Bs[nb][brow + 8][bcol] = nb1;
            __syncthreads();
            cur = nb;
        }
    }
#pragma unroll
    for (int i = 0; i < 8; i++) {
        int m = m0 + (ty << 3) + i;
        int b = m >> 11;
        int irow = m & 2047;
#pragma unroll
        for (int j2 = 0; j2 < 8; j2 += 4) {
            int c = n0 + (tx << 3) + j2;
            int h = c >> 6;
            int d = c & 63;
            float4 v = make_float4(acc[i][j2], acc[i][j2 + 1], acc[i][j2 + 2], acc[i][j2 + 3]);
            if (z == 0)      *(float4*)&g_Q[b][h][irow][d] = v;
            else if (z == 1) *(float4*)&g_K[b][h][NM + irow][d] = v;
            else             *(float4*)&g_V[b][h][NM + irow][d] = v;
        }
    }
}

// ============ dots: per (b,h) 128x128x64 tiles, causal skip (bit-identical) ============
__global__ __launch_bounds__(256, 2) void dots_kernel() {
    const int bh = blockIdx.z;
    const int b = bh >> 4, h = bh & 15;
    const int i0 = blockIdx.y << 7;
    const int j0 = blockIdx.x << 7;
    if (j0 > i0 + 127 + NM) return;
    __shared__ float Qs[64][132];
    __shared__ float Ks[64][132];
    const int tid = threadIdx.x;
    const int ty = tid >> 4, tx = tid & 15;
    const int lr = tid >> 4;
    const int lc = (tid & 15) << 2;
#pragma unroll
    for (int rr = 0; rr < 128; rr += 16) {
        int r = lr + rr;
        float4 q = *(const float4*)&g_Q[b][h][i0 + r][lc];
        Qs[lc + 0][r] = q.x; Qs[lc + 1][r] = q.y;
        Qs[lc + 2][r] = q.z; Qs[lc + 3][r] = q.w;
        int j = j0 + r;
        float4 kv = make_float4(0.f, 0.f, 0.f, 0.f);
        if (j < JTOT) kv = *(const float4*)&g_K[b][h][j][lc];
        Ks[lc + 0][r] = kv.x; Ks[lc + 1][r] = kv.y;
        Ks[lc + 2][r] = kv.z; Ks[lc + 3][r] = kv.w;
    }
    __syncthreads();
    float acc[8][8];
#pragma unroll
    for (int i = 0; i < 8; i++)
#pragma unroll
        for (int j = 0; j < 8; j++) acc[i][j] = 0.f;
#pragma unroll
    for (int kk = 0; kk < 64; kk++) {
        float4 a04 = *(const float4*)&Qs[kk][ty << 3];
        float4 a14 = *(const float4*)&Qs[kk][(ty << 3) + 4];
        float4 b04 = *(const float4*)&Ks[kk][tx << 3];
        float4 b14 = *(const float4*)&Ks[kk][(tx << 3) + 4];
        float av[8] = {a04.x, a04.y, a04.z, a04.w, a14.x, a14.y, a14.z, a14.w};
        float bv[8] = {b04.x, b04.y, b04.z, b04.w, b14.x, b14.y, b14.z, b14.w};
#pragma unroll
        for (int i = 0; i < 8; i++)
#pragma unroll
            for (int j = 0; j < 8; j++) acc[i][j] += av[i] * bv[j];
    }
    const float scale = 0.125f;
#pragma unroll
    for (int i = 0; i < 8; i++) {
        int irow = i0 + (ty << 3) + i;
#pragma unroll
        for (int j2 = 0; j2 < 8; j2 += 4) {
            int jcol = j0 + (tx << 3) + j2;
            if (jcol < JTOT) {
                float4 v = make_float4(acc[i][j2] * scale, acc[i][j2 + 1] * scale,
                                       acc[i][j2 + 2] * scale, acc[i][j2 + 3] * scale);
                *(float4*)&g_dots[b][h][irow][jcol] = v;
            }
        }
    }
}

// ============ fused per-row attention: 1024 threads, reduced-barrier merge ============
#define ATTN_SMEM_FLOATS (H*JTOT + 256 + 256 + H*64*8 + 32 + 16)
#define ATTN_SMEM_INTS   (JTOT + JTOT)
#define ATTN_SMEM_BYTES  ((ATTN_SMEM_FLOATS + ATTN_SMEM_INTS) * 4)

#define INS8(vv) do { float _v = (vv); \
    if (_v > t8[7]) { t8[7] = _v; \
        _Pragma("unroll") \
        for (int _q = 7; _q >= 1; _q--) \
            if (t8[_q] > t8[_q-1]) { float _t = t8[_q]; t8[_q] = t8[_q-1]; t8[_q-1] = _t; } \
    } } while (0)

__global__ __launch_bounds__(1024) void attn_kernel(
    const float* __restrict__ pre, const float* __restrict__ post) {
    const int i = (NSEQ - 1) - blockIdx.x;   // longest rows first
    const int b = blockIdx.y;
    const int tid = threadIdx.x;
    extern __shared__ float sm[];
    float* s_d    = sm;                    // [16][2064] premixed -> exp -> attn2
    float* s_pre  = s_d + H * JTOT;        // [16][16]
    float* s_post = s_pre + 256;           // [16][16]
    float* s_top  = s_post + 256;          // [16 rows][64 lists][8]
    float* s_zred = s_top + H * 64 * 8;    // [32]
    float* s_inv  = s_zred + 32;           // [16]
    int* s_flag = (int*)(s_inv + 16);      // [2064]
    int* s_list = s_flag + JTOT;           // [2064]
    __shared__ int s_wsum[32];

    if (tid < 256) { s_pre[tid] = pre[tid]; s_post[tid] = post[tid]; }
    const int nv = i + NM + 1;  // valid j: [0, nv)
    __syncthreads();

    // ---- fused load + premix + flag zero (reads g_dots directly) ----
    {
        const float* dbase = &g_dots[b][0][i][0];
        const long hstride = (long)NSEQ * JTOT;
        const int npair = (nv + 1) >> 1;
        for (int p = tid; p < npair; p += 1024) {
            int j = p << 1;
            s_flag[j] = 0;
            if (j + 1 < nv) {
                s_flag[j + 1] = 0;
                float2 r[16];
#pragma unroll
                for (int h2 = 0; h2 < 16; h2++)
                    r[h2] = *(const float2*)&dbase[h2 * hstride + j];
#pragma unroll
                for (int k = 0; k < 16; k++) {
                    float a0 = 0.f, a1 = 0.f;
#pragma unroll
                    for (int h2 = 0; h2 < 16; h2++) {
                        float w = s_pre[h2 * 16 + k];
                        a0 += r[h2].x * w;
                        a1 += r[h2].y * w;
                    }
                    *(float2*)&s_d[k * JTOT + j] = make_float2(a0, a1);
                }
            } else {
                float r1[16];
#pragma unroll
                for (int h2 = 0; h2 < 16; h2++) r1[h2] = dbase[h2 * hstride + j];
#pragma unroll
                for (int k = 0; k < 16; k++) {
                    float a = 0.f;
#pragma unroll
                    for (int h2 = 0; h2 < 16; h2++) a += r1[h2] * s_pre[h2 * 16 + k];
                    s_d[k * JTOT + j] = a;
                }
            }
        }
    }
    __syncthreads();

    // ---- top-8 per row: 64 threads per row, float4 scan ----
    const int row = tid >> 6;
    const int t64 = tid & 63;
    const float* rd = s_d + row * JTOT;
    float t8[8];
#pragma unroll
    for (int q = 0; q < 8; q++) t8[q] = -FLT_MAX;
    {
        const int n4 = nv >> 2;
        for (int q = t64; q < n4; q += 64) {
            float4 v4 = *(const float4*)&rd[q << 2];
            INS8(v4.x); INS8(v4.y); INS8(v4.z); INS8(v4.w);
        }
        int tail = nv & 3;
        if (t64 < tail) INS8(rd[(n4 << 2) + t64]);
    }
    {
        float* myl = s_top + (row * 64 + t64) * 8;
#pragma unroll
        for (int q = 0; q < 8; q++) myl[q] = t8[q];
    }
    __syncthreads();
    // ---- merge tree: L=32 cross-warp round (block barrier), then warp-local rounds ----
    if (t64 < 32) {
        float* A  = s_top + (row * 64 + t64) * 8;
        float* B2 = s_top + (row * 64 + t64 + 32) * 8;
        float out[8];
        int ia = 0, ib = 0;
#pragma unroll
        for (int r2 = 0; r2 < 8; r2++) {
            float va = A[ia];
            float vb = B2[ib];
            bool ta = (va >= vb);
            out[r2] = ta ? va : vb;
            ia += ta ? 1 : 0;
            ib += ta ? 0 : 1;
        }
#pragma unroll
        for (int r2 = 0; r2 < 8; r2++) A[r2] = out[r2];
    }
    __syncthreads();
    if (t64 < 32) {
#pragma unroll
        for (int L = 16; L >= 1; L >>= 1) {
            if (t64 < L) {
                float* A  = s_top + (row * 64 + t64) * 8;
                float* B2 = s_top + (row * 64 + t64 + L) * 8;
                float out[8];
                int ia = 0, ib = 0;
#pragma unroll
                for (int r2 = 0; r2 < 8; r2++) {
                    float va = A[ia];
                    float vb = B2[ib];
                    bool ta = (va >= vb);
                    out[r2] = ta ? va : vb;
                    ia += ta ? 1 : 0;
                    ib += ta ? 0 : 1;
                }
#pragma unroll
                for (int r2 = 0; r2 < 8; r2++) A[r2] = out[r2];
            }
            __syncwarp();
        }
    }
    __syncthreads();
    const float thr = s_top[row * 512 + 7];
    const float mx  = s_top[row * 512 + 0];

    // ---- exp-sum pass: write exp(v-mx) for kept, 0 otherwise; set union flags ----
    float psum = 0.f;
    {
        float* wrow = s_d + row * JTOT;
        const int np2 = nv >> 1;
        for (int q = t64; q < np2; q += 64) {
            int j = q << 1;
            float2 v = *(const float2*)&wrow[j];
            bool k0 = (v.x >= thr), k1 = (v.y >= thr);
            float e0 = k0 ? __expf(v.x - mx) : 0.f;
            float e1 = k1 ? __expf(v.y - mx) : 0.f;
            psum += e0; psum += e1;
            *(float2*)&wrow[j] = make_float2(e0, e1);
            if (k0) s_flag[j] = 1;
            if (k1) s_flag[j + 1] = 1;
        }
        if ((nv & 1) && t64 == 0) {
            int j = nv - 1;
            float v = wrow[j];
            if (v >= thr) { float e = __expf(v - mx); psum += e; wrow[j] = e; s_flag[j] = 1; }
            else wrow[j] = 0.f;
        }
    }
#pragma unroll
    for (int off = 16; off >= 1; off >>= 1)
        psum += __shfl_down_sync(0xffffffffu, psum, off);
    if ((tid & 31) == 0) s_zred[tid >> 5] = psum;
    __syncthreads();
    if (t64 == 0) s_inv[row] = 1.f / (s_zred[row * 2] + s_zred[row * 2 + 1]);

    // ---- survivor compaction: 1024-thread two-level scan ----
    const int lane = tid & 31;
    const int wid  = tid >> 5;
    const int CH = 3;  // 1024*3 >= 2064
    int base = tid * CH;
    int end = base + CH; if (end > nv) end = nv;
    int c = 0;
    for (int j = base; j < end; j++) c += s_flag[j];
    int val = c;
#pragma unroll
    for (int off = 1; off < 32; off <<= 1) {
        int u = __shfl_up_sync(0xffffffffu, val, off);
        if (lane >= off) val += u;
    }
    if (lane == 31) s_wsum[wid] = val;
    __syncthreads();
    if (tid < 32) {
        int v = s_wsum[tid];
#pragma unroll
        for (int off = 1; off < 32; off <<= 1) {
            int u = __shfl_up_sync(0xffffffffu, v, off);
            if (tid >= off) v += u;
        }
        s_wsum[tid] = v;
    }
    __syncthreads();
    {
        int pos = (wid > 0 ? s_wsum[wid - 1] : 0) + (val - c);
        for (int j = base; j < end; j++)
            if (s_flag[j]) s_list[pos++] = j;
    }
    const int cnt = s_wsum[31];
    __syncthreads();

    // ---- post-mix at survivor columns (inv folded in) ----
    for (int sI = tid; sI < cnt; sI += 1024) {
        int j = s_list[sI];
        float a[16];
#pragma unroll
        for (int h2 = 0; h2 < 16; h2++) a[h2] = s_d[h2 * JTOT + j] * s_inv[h2];
#pragma unroll
        for (int k = 0; k < 16; k++) {
            float acc2 = 0.f;
#pragma unroll
            for (int h2 = 0; h2 < 16; h2++) acc2 += a[h2] * s_post[h2 * 16 + k];
            s_d[k * JTOT + j] = acc2;
        }
    }
    __syncthreads();

    // ---- sparse attn2 @ V: 64 threads per head, 1 dim each ----
    const int kk2 = tid >> 6;   // head
    const int d = tid & 63;     // dim
    float acc = 0.f;
    const float* Vb = &g_V[b][kk2][0][0];
    const float* wr = s_d + kk2 * JTOT;
    int s2 = 0;
    for (; s2 + 1 < cnt; s2 += 2) {
        int ja = s_list[s2], jb = s_list[s2 + 1];
        float wa = wr[ja], wb = wr[jb];
        acc += wa * Vb[ja * 64 + d] + wb * Vb[jb * 64 + d];
    }
    if (s2 < cnt) {
        int ja = s_list[s2];
        acc += wr[ja] * Vb[ja * 64 + d];
    }
    g_ctx[b][i][kk2 * 64 + d] = acc;
}

// ============ output projection 128x128x16, double-buffered + bias ============
__global__ __launch_bounds__(256, 2) void out_gemm_kernel(
    const float* __restrict__ Wo, const float* __restrict__ bo, float* __restrict__ out) {
    const float* A = &g_ctx[0][0][0];
    __shared__ float As[2][16][132];
    __shared__ float Bs[2][16][132];
    const int m0 = blockIdx.y << 7;
    const int n0 = blockIdx.x << 7;
    const int tid = threadIdx.x;
    const int ty = tid >> 4, tx = tid & 15;
    const int arow = tid >> 2, acol = (tid & 3) << 2;
    const int brow = tid >> 5, bcol = (tid & 31) << 2;
    float acc[8][8];
#pragma unroll
    for (int i = 0; i < 8; i++)
#pragma unroll
        for (int j = 0; j < 8; j++) acc[i][j] = 0.f;

    {
        float4 a0 = *(const float4*)&A[(m0 + arow) * DIM + acol];
        float4 a1 = *(const float4*)&A[(m0 + arow + 64) * DIM + acol];
        float4 b0 = *(const float4*)&Wo[brow * DIM + n0 + bcol];
        float4 b1 = *(const float4*)&Wo[(brow + 8) * DIM + n0 + bcol];
        As[0][acol + 0][arow] = a0.x; As[0][acol + 1][arow] = a0.y;
        As[0][acol + 2][arow] = a0.z; As[0][acol + 3][arow] = a0.w;
        As[0][acol + 0][arow + 64] = a1.x; As[0][acol + 1][arow + 64] = a1.y;
        As[0][acol + 2][arow + 64] = a1.z; As[0][acol + 3][arow + 64] = a1.w;
        *(float4*)&Bs[0][brow][bcol] = b0;
        *(float4*)&Bs[0][brow + 8][bcol] = b1;
    }
    __syncthreads();

    int cur = 0;
    for (int k0 = 0; k0 < DIM; k0 += 16) {
        const int nxt = k0 + 16;
        float4 na0, na1, nb0, nb1;
        if (nxt < DIM) {
            na0 = *(const float4*)&A[(m0 + arow) * DIM + nxt + acol];
            na1 = *(const float4*)&A[(m0 + arow + 64) * DIM + nxt + acol];
            nb0 = *(const float4*)&Wo[(nxt + brow) * DIM + n0 + bcol];
            nb1 = *(const float4*)&Wo[(nxt + brow + 8) * DIM + n0 + bcol];
        }
#pragma unroll
        for (int kk = 0; kk < 16; kk++) {
            float4 a04 = *(const float4*)&As[cur][kk][ty << 3];
            float4 a14 = *(const float4*)&As[cur][kk][(ty << 3) + 4];
            float4 b04 = *(const float4*)&Bs[cur][kk][tx << 3];
            float4 b14 = *(const float4*)&Bs[cur][kk][(tx << 3) + 4];
            float av[8] = {a04.x, a04.y, a04.z, a04.w, a14.x, a14.y, a14.z, a14.w};
            float bv[8] = {b04.x, b04.y, b04.z, b04.w, b14.x, b14.y, b14.z, b14.w};
#pragma unroll
            for (int i = 0; i < 8; i++)
#pragma unroll
                for (int j = 0; j < 8; j++) acc[i][j] += av[i] * bv[j];
        }
        if (nxt < DIM) {
            const int nb = cur ^ 1;
            As[nb][acol + 0][arow] = na0.x; As[nb][acol + 1][arow] = na0.y;
            As[nb][acol + 2][arow] = na0.z; As[nb][acol + 3][arow] = na0.w;
            As[nb][acol + 0][arow + 64] = na1.x; As[nb][acol + 1][arow + 64] = na1.y;
            As[nb][acol + 2][arow + 64] = na1.z; As[nb][acol + 3][arow + 64] = na1.w;
            *(float4*)&Bs[nb][brow][bcol] = nb0;
            *(float4*)&Bs[nb][brow + 8][bcol] = nb1;
            __syncthreads();
            cur = nb;
        }
    }
#pragma unroll
    for (int i = 0; i < 8; i++) {
        int m = m0 + (ty << 3) + i;
#pragma unroll
        for (int j2 = 0; j2 < 8; j2 += 4) {
            int c = n0 + (tx << 3) + j2;
            float4 bias = *(const float4*)&bo[c];
            float4 v = make_float4(acc[i][j2] + bias.x, acc[i][j2 + 1] + bias.y,
                                   acc[i][j2 + 2] + bias.z, acc[i][j2 + 3] + bias.w);
            *(float4*)&out[m * DIM + c] = v;
        }
    }
}

// ---------------- launch ----------------
extern "C" void kernel_launch(void* const* d_in, const int* in_sizes, int n_in,
                              void* d_out, int out_size) {
    const float* x    = (const float*)d_in[0];
    const float* Wq   = (const float*)d_in[1];
    const float* Wk   = (const float*)d_in[2];
    const float* Wv   = (const float*)d_in[3];
    const float* pre  = (const float*)d_in[4];
    const float* post = (const float*)d_in[5];
    const float* mk   = (const float*)d_in[6];
    const float* mv   = (const float*)d_in[7];
    const float* Wo   = (const float*)d_in[8];
    const float* bo   = (const float*)d_in[9];
    float* out = (float*)d_out;

    cudaFuncSetAttribute(attn_kernel, cudaFuncAttributeMaxDynamicSharedMemorySize, ATTN_SMEM_BYTES);

    memfill_kernel<<<(BATCH * H * NM * DH + 255) / 256, 256>>>(mk, mv);
    gemm_qkv_kernel<<<dim3(DIM / 128, MROWS / 128, 3), 256>>>(x, Wq, Wk, Wv);
    dots_kernel<<<dim3((JTOT + 127) / 128, NSEQ / 128, BATCH * H), 256>>>();
    attn_kernel<<<dim3(NSEQ, BATCH), 1024, ATTN_SMEM_BYTES>>>(pre, post);
    out_gemm_kernel<<<dim3(DIM / 128, MROWS / 128), 256>>>(Wo, bo, out);
}

// round 11
// speedup vs baseline: 1.6006x; 1.0427x over previous
#include <cuda_runtime.h>
#include <cuda_bf16.h>
#include <mma.h>
#include <float.h>
#include <math.h>

using namespace nvcuda;
typedef __nv_bfloat16 bf16;

#define BATCH 2
#define NSEQ  2048
#define DIM   1024
#define H     16
#define DH    64
#define NM    16
#define JTOT  2064          // NM + NSEQ
#define MROWS (BATCH*NSEQ)  // 4096

// ---------------- global scratch ----------------
__device__ float g_Q[BATCH][H][NSEQ][DH];
__device__ float g_K[BATCH][H][JTOT][DH];
__device__ float g_V[BATCH][H][JTOT][DH];
__device__ float g_dots[BATCH][H][NSEQ][JTOT];
__device__ bf16  g_xh[MROWS*DIM],  g_xl[MROWS*DIM];
__device__ bf16  g_Wvh[DIM*DIM],   g_Wvl[DIM*DIM];
__device__ bf16  g_Woh[DIM*DIM],   g_Wol[DIM*DIM];
__device__ bf16  g_ctxh[MROWS*DIM], g_ctxl[MROWS*DIM];

__device__ __forceinline__ void bsplit2(float v, bf16& h, bf16& l) {
    h = __float2bfloat16(v);
    l = __float2bfloat16(v - __bfloat162float(h));
}

// ---------------- fill mem_k / mem_v into K/V prefix ----------------
__global__ void memfill_kernel(const float* __restrict__ mk, const float* __restrict__ mv) {
    int idx = blockIdx.x * 256 + threadIdx.x;
    if (idx >= BATCH * H * NM * DH) return;
    int d = idx & 63;
    int j = (idx >> 6) & 15;
    int h = (idx >> 10) & 15;
    int b = idx >> 14;
    g_K[b][h][j][d] = mk[(h * NM + j) * DH + d];
    g_V[b][h][j][d] = mv[(h * NM + j) * DH + d];
}

// ---------------- bf16 hi/lo split ----------------
__global__ void split2(const float* __restrict__ s, bf16* __restrict__ h,
                       bf16* __restrict__ l, int n) {
    int i = blockIdx.x * 256 + threadIdx.x;
    if (i >= n) return;
    bf16 a, c; bsplit2(s[i], a, c);
    h[i] = a; l[i] = c;
}

// ============ 128x128x16 fp32 GEMM (Q,K only — bit-identical path) ============
__global__ __launch_bounds__(256, 2) void gemm_qkv_kernel(
    const float* __restrict__ x, const float* __restrict__ Wq,
    const float* __restrict__ Wk, const float* __restrict__ Wv) {
    const int z = blockIdx.z;
    const float* W = (z == 0) ? Wq : (z == 1) ? Wk : Wv;
    __shared__ float As[2][16][132];
    __shared__ float Bs[2][16][132];
    const int m0 = blockIdx.y << 7;
    const int n0 = blockIdx.x << 7;
    const int tid = threadIdx.x;
    const int ty = tid >> 4, tx = tid & 15;
    const int arow = tid >> 2, acol = (tid & 3) << 2;
    const int brow = tid >> 5, bcol = (tid & 31) << 2;
    float acc[8][8];
#pragma unroll
    for (int i = 0; i < 8; i++)
#pragma unroll
        for (int j = 0; j < 8; j++) acc[i][j] = 0.f;

    {
        float4 a0 = *(const float4*)&x[(m0 + arow) * DIM + acol];
        float4 a1 = *(const float4*)&x[(m0 + arow + 64) * DIM + acol];
        float4 b0 = *(const float4*)&W[brow * DIM + n0 + bcol];
        float4 b1 = *(const float4*)&W[(brow + 8) * DIM + n0 + bcol];
        As[0][acol + 0][arow] = a0.x; As[0][acol + 1][arow] = a0.y;
        As[0][acol + 2][arow] = a0.z; As[0][acol + 3][arow] = a0.w;
        As[0][acol + 0][arow + 64] = a1.x; As[0][acol + 1][arow + 64] = a1.y;
        As[0][acol + 2][arow + 64] = a1.z; As[0][acol + 3][arow + 64] = a1.w;
        *(float4*)&Bs[0][brow][bcol] = b0;
        *(float4*)&Bs[0][brow + 8][bcol] = b1;
    }
    __syncthreads();

    int cur = 0;
    for (int k0 = 0; k0 < DIM; k0 += 16) {
        const int nxt = k0 + 16;
        float4 na0, na1, nb0, nb1;
        if (nxt < DIM) {
            na0 = *(const float4*)&x[(m0 + arow) * DIM + nxt + acol];
            na1 = *(const float4*)&x[(m0 + arow + 64) * DIM + nxt + acol];
            nb0 = *(const float4*)&W[(nxt + brow) * DIM + n0 + bcol];
            nb1 = *(const float4*)&W[(nxt + brow + 8) * DIM + n0 + bcol];
        }
#pragma unroll
        for (int kk = 0; kk < 16; kk++) {
            float4 a04 = *(const float4*)&As[cur][kk][ty << 3];
            float4 a14 = *(const float4*)&As[cur][kk][(ty << 3) + 4];
            float4 b04 = *(const float4*)&Bs[cur][kk][tx << 3];
            float4 b14 = *(const float4*)&Bs[cur][kk][(tx << 3) + 4];
            float av[8] = {a04.x, a04.y, a04.z, a04.w, a14.x, a14.y, a14.z, a14.w};
            float bv[8] = {b04.x, b04.y, b04.z, b04.w, b14.x, b14.y, b14.z, b14.w};
#pragma unroll
            for (int i = 0; i < 8; i++)
#pragma unroll
                for (int j = 0; j < 8; j++) acc[i][j] += av[i] * bv[j];
        }
        if (nxt < DIM) {
            const int nb = cur ^ 1;
            As[nb][acol + 0][arow] = na0.x; As[nb][acol + 1][arow] = na0.y;
            As[nb][acol + 2][arow] = na0.z; As[nb][acol + 3][arow] = na0.w;
            As[nb][acol + 0][arow + 64] = na1.x; As[nb][acol + 1][arow + 64] = na1.y;
            As[nb][acol + 2][arow + 64] = na1.z; As[nb][acol + 3][arow + 64] = na1.w;
            *(float4*)&Bs[nb][brow][bcol] = nb0;
            *(float4*)&Bs[nb][brow + 8][bcol] = nb1;
            __syncthreads();
            cur = nb;
        }
    }
#pragma unroll
    for (int i = 0; i < 8; i++) {
        int m = m0 + (ty << 3) + i;
        int b = m >> 11;
        int irow = m & 2047;
#pragma unroll
        for (int j2 = 0; j2 < 8; j2 += 4) {
            int c = n0 + (tx << 3) + j2;
            int h = c >> 6;
            int d = c & 63;
            float4 v = make_float4(acc[i][j2], acc[i][j2 + 1], acc[i][j2 + 2], acc[i][j2 + 3]);
            if (z == 0)      *(float4*)&g_Q[b][h][irow][d] = v;
            else if (z == 1) *(float4*)&g_K[b][h][NM + irow][d] = v;
            else             *(float4*)&g_V[b][h][NM + irow][d] = v;
        }
    }
}

// ============ V projection: bf16x3 wmma, BM=128 BN=64 BK=32 (linear path) ============
__global__ __launch_bounds__(256) void v_wmma() {
    __shared__ bf16 sAh[128 * 40], sAl[128 * 40];
    __shared__ bf16 sBh[32 * 72],  sBl[32 * 72];
    const int m0 = blockIdx.y << 7;
    const int n0 = blockIdx.x << 6;
    const int tid = threadIdx.x;
    const int w = tid >> 5;
    const int wm = w >> 1, wn = w & 1;

    wmma::fragment<wmma::accumulator, 16, 16, 16, float> acc[2][2];
#pragma unroll
    for (int i = 0; i < 2; i++)
#pragma unroll
        for (int j = 0; j < 2; j++) wmma::fill_fragment(acc[i][j], 0.f);

    for (int k0 = 0; k0 < DIM; k0 += 32) {
        __syncthreads();
#pragma unroll
        for (int it = 0; it < 4; it++) {
            int idx = tid + it * 256;
            int r = idx >> 3, c = (idx & 7) << 2;
            long g = (long)(m0 + r) * DIM + k0 + c;
            *(uint2*)&sAh[r * 40 + c] = *(const uint2*)&g_xh[g];
            *(uint2*)&sAl[r * 40 + c] = *(const uint2*)&g_xl[g];
        }
#pragma unroll
        for (int it = 0; it < 2; it++) {
            int idx = tid + it * 256;
            int r = idx >> 4, c = (idx & 15) << 2;
            long g = (long)(k0 + r) * DIM + n0 + c;
            *(uint2*)&sBh[r * 72 + c] = *(const uint2*)&g_Wvh[g];
            *(uint2*)&sBl[r * 72 + c] = *(const uint2*)&g_Wvl[g];
        }
        __syncthreads();
#pragma unroll
        for (int ks = 0; ks < 2; ks++) {
            int k = ks << 4;
            wmma::fragment<wmma::matrix_a, 16, 16, 16, bf16, wmma::row_major> ah[2], al[2];
            wmma::fragment<wmma::matrix_b, 16, 16, 16, bf16, wmma::row_major> bh[2], bl[2];
#pragma unroll
            for (int fm = 0; fm < 2; fm++) {
                wmma::load_matrix_sync(ah[fm], &sAh[(wm * 32 + fm * 16) * 40 + k], 40);
                wmma::load_matrix_sync(al[fm], &sAl[(wm * 32 + fm * 16) * 40 + k], 40);
            }
#pragma unroll
            for (int fn = 0; fn < 2; fn++) {
                wmma::load_matrix_sync(bh[fn], &sBh[k * 72 + wn * 32 + fn * 16], 72);
                wmma::load_matrix_sync(bl[fn], &sBl[k * 72 + wn * 32 + fn * 16], 72);
            }
#pragma unroll
            for (int fm = 0; fm < 2; fm++)
#pragma unroll
                for (int fn = 0; fn < 2; fn++) {
                    wmma::mma_sync(acc[fm][fn], ah[fm], bl[fn], acc[fm][fn]);
                    wmma::mma_sync(acc[fm][fn], al[fm], bh[fn], acc[fm][fn]);
                    wmma::mma_sync(acc[fm][fn], ah[fm], bh[fn], acc[fm][fn]);
                }
        }
    }
    const int h = n0 >> 6;
#pragma unroll
    for (int fm = 0; fm < 2; fm++) {
        int m = m0 + wm * 32 + fm * 16;
        int b = m >> 11;
        int irow = m & 2047;
#pragma unroll
        for (int fn = 0; fn < 2; fn++) {
            int d = wn * 32 + fn * 16;
            wmma::store_matrix_sync(&g_V[b][h][NM + irow][d], acc[fm][fn], DH, wmma::mem_row_major);
        }
    }
}

// ============ dots: per (b,h) 128x128x64 tiles, causal skip (bit-identical) ============
__global__ __launch_bounds__(256, 2) void dots_kernel() {
    const int bh = blockIdx.z;
    const int b = bh >> 4, h = bh & 15;
    const int i0 = blockIdx.y << 7;
    const int j0 = blockIdx.x << 7;
    if (j0 > i0 + 127 + NM) return;
    __shared__ float Qs[64][132];
    __shared__ float Ks[64][132];
    const int tid = threadIdx.x;
    const int ty = tid >> 4, tx = tid & 15;
    const int lr = tid >> 4;
    const int lc = (tid & 15) << 2;
#pragma unroll
    for (int rr = 0; rr < 128; rr += 16) {
        int r = lr + rr;
        float4 q = *(const float4*)&g_Q[b][h][i0 + r][lc];
        Qs[lc + 0][r] = q.x; Qs[lc + 1][r] = q.y;
        Qs[lc + 2][r] = q.z; Qs[lc + 3][r] = q.w;
        int j = j0 + r;
        float4 kv = make_float4(0.f, 0.f, 0.f, 0.f);
        if (j < JTOT) kv = *(const float4*)&g_K[b][h][j][lc];
        Ks[lc + 0][r] = kv.x; Ks[lc + 1][r] = kv.y;
        Ks[lc + 2][r] = kv.z; Ks[lc + 3][r] = kv.w;
    }
    __syncthreads();
    float acc[8][8];
#pragma unroll
    for (int i = 0; i < 8; i++)
#pragma unroll
        for (int j = 0; j < 8; j++) acc[i][j] = 0.f;
#pragma unroll
    for (int kk = 0; kk < 64; kk++) {
        float4 a04 = *(const float4*)&Qs[kk][ty << 3];
        float4 a14 = *(const float4*)&Qs[kk][(ty << 3) + 4];
        float4 b04 = *(const float4*)&Ks[kk][tx << 3];
        float4 b14 = *(const float4*)&Ks[kk][(tx << 3) + 4];
        float av[8] = {a04.x, a04.y, a04.z, a04.w, a14.x, a14.y, a14.z, a14.w};
        float bv[8] = {b04.x, b04.y, b04.z, b04.w, b14.x, b14.y, b14.z, b14.w};
#pragma unroll
        for (int i = 0; i < 8; i++)
#pragma unroll
            for (int j = 0; j < 8; j++) acc[i][j] += av[i] * bv[j];
    }
    const float scale = 0.125f;
#pragma unroll
    for (int i = 0; i < 8; i++) {
        int irow = i0 + (ty << 3) + i;
#pragma unroll
        for (int j2 = 0; j2 < 8; j2 += 4) {
            int jcol = j0 + (tx << 3) + j2;
            if (jcol < JTOT) {
                float4 v = make_float4(acc[i][j2] * scale, acc[i][j2 + 1] * scale,
                                       acc[i][j2 + 2] * scale, acc[i][j2 + 3] * scale);
                *(float4*)&g_dots[b][h][irow][jcol] = v;
            }
        }
    }
}

// ============ fused per-row attention: 1024 threads (unchanged core) ============
#define ATTN_SMEM_FLOATS (H*JTOT + 256 + 256 + H*64*8 + 32 + 16)
#define ATTN_SMEM_INTS   (JTOT + JTOT)
#define ATTN_SMEM_BYTES  ((ATTN_SMEM_FLOATS + ATTN_SMEM_INTS) * 4)

#define INS8(vv) do { float _v = (vv); \
    if (_v > t8[7]) { t8[7] = _v; \
        _Pragma("unroll") \
        for (int _q = 7; _q >= 1; _q--) \
            if (t8[_q] > t8[_q-1]) { float _t = t8[_q]; t8[_q] = t8[_q-1]; t8[_q-1] = _t; } \
    } } while (0)

__global__ __launch_bounds__(1024) void attn_kernel(
    const float* __restrict__ pre, const float* __restrict__ post) {
    const int i = (NSEQ - 1) - blockIdx.x;
    const int b = blockIdx.y;
    const int tid = threadIdx.x;
    extern __shared__ float sm[];
    float* s_d    = sm;
    float* s_pre  = s_d + H * JTOT;
    float* s_post = s_pre + 256;
    float* s_top  = s_post + 256;
    float* s_zred = s_top + H * 64 * 8;
    float* s_inv  = s_zred + 32;
    int* s_flag = (int*)(s_inv + 16);
    int* s_list = s_flag + JTOT;
    __shared__ int s_wsum[32];

    if (tid < 256) { s_pre[tid] = pre[tid]; s_post[tid] = post[tid]; }
    const int nv = i + NM + 1;
    __syncthreads();

    {
        const float* dbase = &g_dots[b][0][i][0];
        const long hstride = (long)NSEQ * JTOT;
        const int npair = (nv + 1) >> 1;
        for (int p = tid; p < npair; p += 1024) {
            int j = p << 1;
            s_flag[j] = 0;
            if (j + 1 < nv) {
                s_flag[j + 1] = 0;
                float2 r[16];
#pragma unroll
                for (int h2 = 0; h2 < 16; h2++)
                    r[h2] = *(const float2*)&dbase[h2 * hstride + j];
#pragma unroll
                for (int k = 0; k < 16; k++) {
                    float a0 = 0.f, a1 = 0.f;
#pragma unroll
                    for (int h2 = 0; h2 < 16; h2++) {
                        float w = s_pre[h2 * 16 + k];
                        a0 += r[h2].x * w;
                        a1 += r[h2].y * w;
                    }
                    *(float2*)&s_d[k * JTOT + j] = make_float2(a0, a1);
                }
            } else {
                float r1[16];
#pragma unroll
                for (int h2 = 0; h2 < 16; h2++) r1[h2] = dbase[h2 * hstride + j];
#pragma unroll
                for (int k = 0; k < 16; k++) {
                    float a = 0.f;
#pragma unroll
                    for (int h2 = 0; h2 < 16; h2++) a += r1[h2] * s_pre[h2 * 16 + k];
                    s_d[k * JTOT + j] = a;
                }
            }
        }
    }
    __syncthreads();

    const int row = tid >> 6;
    const int t64 = tid & 63;
    const float* rd = s_d + row * JTOT;
    float t8[8];
#pragma unroll
    for (int q = 0; q < 8; q++) t8[q] = -FLT_MAX;
    {
        const int n4 = nv >> 2;
        for (int q = t64; q < n4; q += 64) {
            float4 v4 = *(const float4*)&rd[q << 2];
            INS8(v4.x); INS8(v4.y); INS8(v4.z); INS8(v4.w);
        }
        int tail = nv & 3;
        if (t64 < tail) INS8(rd[(n4 << 2) + t64]);
    }
    {
        float* myl = s_top + (row * 64 + t64) * 8;
#pragma unroll
        for (int q = 0; q < 8; q++) myl[q] = t8[q];
    }
    __syncthreads();
    if (t64 < 32) {
        float* A  = s_top + (row * 64 + t64) * 8;
        float* B2 = s_top + (row * 64 + t64 + 32) * 8;
        float out[8];
        int ia = 0, ib = 0;
#pragma unroll
        for (int r2 = 0; r2 < 8; r2++) {
            float va = A[ia];
            float vb = B2[ib];
            bool ta = (va >= vb);
            out[r2] = ta ? va : vb;
            ia += ta ? 1 : 0;
            ib += ta ? 0 : 1;
        }
#pragma unroll
        for (int r2 = 0; r2 < 8; r2++) A[r2] = out[r2];
    }
    __syncthreads();
    if (t64 < 32) {
#pragma unroll
        for (int L = 16; L >= 1; L >>= 1) {
            if (t64 < L) {
                float* A  = s_top + (row * 64 + t64) * 8;
                float* B2 = s_top + (row * 64 + t64 + L) * 8;
                float out[8];
                int ia = 0, ib = 0;
#pragma unroll
                for (int r2 = 0; r2 < 8; r2++) {
                    float va = A[ia];
                    float vb = B2[ib];
                    bool ta = (va >= vb);
                    out[r2] = ta ? va : vb;
                    ia += ta ? 1 : 0;
                    ib += ta ? 0 : 1;
                }
#pragma unroll
                for (int r2 = 0; r2 < 8; r2++) A[r2] = out[r2];
            }
            __syncwarp();
        }
    }
    __syncthreads();
    const float thr = s_top[row * 512 + 7];
    const float mx  = s_top[row * 512 + 0];

    float psum = 0.f;
    {
        float* wrow = s_d + row * JTOT;
        const int np2 = nv >> 1;
        for (int q = t64; q < np2; q += 64) {
            int j = q << 1;
            float2 v = *(const float2*)&wrow[j];
            bool k0 = (v.x >= thr), k1 = (v.y >= thr);
            float e0 = k0 ? __expf(v.x - mx) : 0.f;
            float e1 = k1 ? __expf(v.y - mx) : 0.f;
            psum += e0; psum += e1;
            *(float2*)&wrow[j] = make_float2(e0, e1);
            if (k0) s_flag[j] = 1;
            if (k1) s_flag[j + 1] = 1;
        }
        if ((nv & 1) && t64 == 0) {
            int j = nv - 1;
            float v = wrow[j];
            if (v >= thr) { float e = __expf(v - mx); psum += e; wrow[j] = e; s_flag[j] = 1; }
            else wrow[j] = 0.f;
        }
    }
#pragma unroll
    for (int off = 16; off >= 1; off >>= 1)
        psum += __shfl_down_sync(0xffffffffu, psum, off);
    if ((tid & 31) == 0) s_zred[tid >> 5] = psum;
    __syncthreads();
    if (t64 == 0) s_inv[row] = 1.f / (s_zred[row * 2] + s_zred[row * 2 + 1]);

    const int lane = tid & 31;
    const int wid  = tid >> 5;
    const int CH = 3;
    int base = tid * CH;
    int end = base + CH; if (end > nv) end = nv;
    int c = 0;
    for (int j = base; j < end; j++) c += s_flag[j];
    int val = c;
#pragma unroll
    for (int off = 1; off < 32; off <<= 1) {
        int u = __shfl_up_sync(0xffffffffu, val, off);
        if (lane >= off) val += u;
    }
    if (lane == 31) s_wsum[wid] = val;
    __syncthreads();
    if (tid < 32) {
        int v = s_wsum[tid];
#pragma unroll
        for (int off = 1; off < 32; off <<= 1) {
            int u = __shfl_up_sync(0xffffffffu, v, off);
            if (tid >= off) v += u;
        }
        s_wsum[tid] = v;
    }
    __syncthreads();
    {
        int pos = (wid > 0 ? s_wsum[wid - 1] : 0) + (val - c);
        for (int j = base; j < end; j++)
            if (s_flag[j]) s_list[pos++] = j;
    }
    const int cnt = s_wsum[31];
    __syncthreads();

    for (int sI = tid; sI < cnt; sI += 1024) {
        int j = s_list[sI];
        float a[16];
#pragma unroll
        for (int h2 = 0; h2 < 16; h2++) a[h2] = s_d[h2 * JTOT + j] * s_inv[h2];
#pragma unroll
        for (int k = 0; k < 16; k++) {
            float acc2 = 0.f;
#pragma unroll
            for (int h2 = 0; h2 < 16; h2++) acc2 += a[h2] * s_post[h2 * 16 + k];
            s_d[k * JTOT + j] = acc2;
        }
    }
    __syncthreads();

    const int kk2 = tid >> 6;   // head
    const int d = tid & 63;     // dim
    float acc = 0.f;
    const float* Vb = &g_V[b][kk2][0][0];
    const float* wr = s_d + kk2 * JTOT;
    int s2 = 0;
    for (; s2 + 1 < cnt; s2 += 2) {
        int ja = s_list[s2], jb = s_list[s2 + 1];
        float wa = wr[ja], wb = wr[jb];
        acc += wa * Vb[ja * 64 + d] + wb * Vb[jb * 64 + d];
    }
    if (s2 < cnt) {
        int ja = s_list[s2];
        acc += wr[ja] * Vb[ja * 64 + d];
    }
    // store ctx as bf16 hi/lo (for bf16x3 out projection)
    bf16 hx, lx;
    bsplit2(acc, hx, lx);
    long off2 = (long)(b * NSEQ + i) * DIM + kk2 * 64 + d;
    g_ctxh[off2] = hx;
    g_ctxl[off2] = lx;
}

// ============ output projection: bf16x3 wmma + bias (linear path) ============
__global__ __launch_bounds__(256) void out_wmma(const float* __restrict__ bo,
                                                float* __restrict__ outp) {
    __shared__ float sEpi[128 * 72];      // aliased for loads
    bf16* sAh = (bf16*)sEpi;              // 128*40
    bf16* sAl = sAh + 128 * 40;
    bf16* sBh = sAl + 128 * 40;           // 32*72
    bf16* sBl = sBh + 32 * 72;
    const int m0 = blockIdx.y << 7;
    const int n0 = blockIdx.x << 6;
    const int tid = threadIdx.x;
    const int w = tid >> 5;
    const int wm = w >> 1, wn = w & 1;

    wmma::fragment<wmma::accumulator, 16, 16, 16, float> acc[2][2];
#pragma unroll
    for (int i = 0; i < 2; i++)
#pragma unroll
        for (int j = 0; j < 2; j++) wmma::fill_fragment(acc[i][j], 0.f);

    for (int k0 = 0; k0 < DIM; k0 += 32) {
        __syncthreads();
#pragma unroll
        for (int it = 0; it < 4; it++) {
            int idx = tid + it * 256;
            int r = idx >> 3, c = (idx & 7) << 2;
            long g = (long)(m0 + r) * DIM + k0 + c;
            *(uint2*)&sAh[r * 40 + c] = *(const uint2*)&g_ctxh[g];
            *(uint2*)&sAl[r * 40 + c] = *(const uint2*)&g_ctxl[g];
        }
#pragma unroll
        for (int it = 0; it < 2; it++) {
            int idx = tid + it * 256;
            int r = idx >> 4, c = (idx & 15) << 2;
            long g = (long)(k0 + r) * DIM + n0 + c;
            *(uint2*)&sBh[r * 72 + c] = *(const uint2*)&g_Woh[g];
            *(uint2*)&sBl[r * 72 + c] = *(const uint2*)&g_Wol[g];
        }
        __syncthreads();
#pragma unroll
        for (int ks = 0; ks < 2; ks++) {
            int k = ks << 4;
            wmma::fragment<wmma::matrix_a, 16, 16, 16, bf16, wmma::row_major> ah[2], al[2];
            wmma::fragment<wmma::matrix_b, 16, 16, 16, bf16, wmma::row_major> bh[2], bl[2];
#pragma unroll
            for (int fm = 0; fm < 2; fm++) {
                wmma::load_matrix_sync(ah[fm], &sAh[(wm * 32 + fm * 16) * 40 + k], 40);
                wmma::load_matrix_sync(al[fm], &sAl[(wm * 32 + fm * 16) * 40 + k], 40);
            }
#pragma unroll
            for (int fn = 0; fn < 2; fn++) {
                wmma::load_matrix_sync(bh[fn], &sBh[k * 72 + wn * 32 + fn * 16], 72);
                wmma::load_matrix_sync(bl[fn], &sBl[k * 72 + wn * 32 + fn * 16], 72);
            }
#pragma unroll
            for (int fm = 0; fm < 2; fm++)
#pragma unroll
                for (int fn = 0; fn < 2; fn++) {
                    wmma::mma_sync(acc[fm][fn], ah[fm], bl[fn], acc[fm][fn]);
                    wmma::mma_sync(acc[fm][fn], al[fm], bh[fn], acc[fm][fn]);
                    wmma::mma_sync(acc[fm][fn], ah[fm], bh[fn], acc[fm][fn]);
                }
        }
    }
    __syncthreads();
#pragma unroll
    for (int fm = 0; fm < 2; fm++)
#pragma unroll
        for (int fn = 0; fn < 2; fn++)
            wmma::store_matrix_sync(&sEpi[(wm * 32 + fm * 16) * 72 + wn * 32 + fn * 16],
                                    acc[fm][fn], 72, wmma::mem_row_major);
    __syncthreads();
#pragma unroll
    for (int it = 0; it < 8; it++) {
        int idx = tid + it * 256;
        int r = idx >> 4, c = (idx & 15) << 2;
        float4 v = *(const float4*)&sEpi[r * 72 + c];
        float4 bias = *(const float4*)&bo[n0 + c];
        v.x += bias.x; v.y += bias.y; v.z += bias.z; v.w += bias.w;
        *(float4*)&outp[(m0 + r) * DIM + n0 + c] = v;
    }
}

// ---------------- launch ----------------
extern "C" void kernel_launch(void* const* d_in, const int* in_sizes, int n_in,
                              void* d_out, int out_size) {
    const float* x    = (const float*)d_in[0];
    const float* Wq   = (const float*)d_in[1];
    const float* Wk   = (const float*)d_in[2];
    const float* Wv   = (const float*)d_in[3];
    const float* pre  = (const float*)d_in[4];
    const float* post = (const float*)d_in[5];
    const float* mk   = (const float*)d_in[6];
    const float* mv   = (const float*)d_in[7];
    const float* Wo   = (const float*)d_in[8];
    const float* bo   = (const float*)d_in[9];
    float* out = (float*)d_out;

    cudaFuncSetAttribute(attn_kernel, cudaFuncAttributeMaxDynamicSharedMemorySize, ATTN_SMEM_BYTES);

    bf16 *xh, *xl, *wvh, *wvl, *woh, *wol;
    cudaGetSymbolAddress((void**)&xh,  g_xh);  cudaGetSymbolAddress((void**)&xl,  g_xl);
    cudaGetSymbolAddress((void**)&wvh, g_Wvh); cudaGetSymbolAddress((void**)&wvl, g_Wvl);
    cudaGetSymbolAddress((void**)&woh, g_Woh); cudaGetSymbolAddress((void**)&wol, g_Wol);

    memfill_kernel<<<(BATCH * H * NM * DH + 255) / 256, 256>>>(mk, mv);
    split2<<<(MROWS * DIM + 255) / 256, 256>>>(x,  xh,  xl,  MROWS * DIM);
    split2<<<(DIM * DIM + 255) / 256, 256>>>(Wv, wvh, wvl, DIM * DIM);
    split2<<<(DIM * DIM + 255) / 256, 256>>>(Wo, woh, wol, DIM * DIM);

    gemm_qkv_kernel<<<dim3(DIM / 128, MROWS / 128, 2), 256>>>(x, Wq, Wk, Wv);  // Q,K fp32
    v_wmma<<<dim3(DIM / 64, MROWS / 128), 256>>>();                            // V bf16x3
    dots_kernel<<<dim3((JTOT + 127) / 128, NSEQ / 128, BATCH * H), 256>>>();
    attn_kernel<<<dim3(NSEQ, BATCH), 1024, ATTN_SMEM_BYTES>>>(pre, post);
    out_wmma<<<dim3(DIM / 64, MROWS / 128), 256>>>(bo, out);                   // out bf16x3
}